// round 13
// baseline (speedup 1.0000x reference)
#include <cuda_runtime.h>
#include <cuda_bf16.h>
#include <cuda_fp16.h>
#include <cstdint>
#include <math.h>

// ---------------------------------------------------------------------------
// Problem constants
// ---------------------------------------------------------------------------
constexpr int B_  = 2;
constexpr int NQ  = 2048;
constexpr int NC  = 4096;
constexpr int CE  = 512;
constexpr int H_  = 8;
constexpr float SCALE  = 0.125f;
constexpr float FOURNU = 0.4f;
constexpr float EPS_   = 1e-6f;

// Pair-interleave permutation within a 16-element k-chunk (validated R7+).
__host__ __device__ constexpr int perm16(int e) {
    int lp = e >> 1, o = e & 1;
    int slot = (lp < 4) ? (lp * 2) : ((lp - 4) * 2 + 1);
    return slot * 2 + o;
}

// ---------------------------------------------------------------------------
// Scratch
// g_khl: [b*NC + c][head*128 + ks*32 + tg*8 + {hi:0..3, lo:4..7}]  (1024/row)
// g_vhl: [(b*H+h)*64 + d][(c chunk)*32 + tg*8 + {hi,lo}]           (NC*2/row)
// ---------------------------------------------------------------------------
__device__ __half g_heat[(size_t)B_ * NQ * NC];           // 33.5 MB (fp16)
__device__ __nv_bfloat16 g_xqh[B_ * NQ * CE];
__device__ __nv_bfloat16 g_xql[B_ * NQ * CE];
__device__ __nv_bfloat16 g_xch[B_ * NC * CE];
__device__ __nv_bfloat16 g_xcl[B_ * NC * CE];
__device__ __nv_bfloat16 g_wh[4 * CE * CE];
__device__ __nv_bfloat16 g_wl[4 * CE * CE];
__device__ __nv_bfloat16 g_qh[B_ * NQ * CE];              // scaled, d-permuted
__device__ __nv_bfloat16 g_ql[B_ * NQ * CE];
__device__ __nv_bfloat16 g_khl[(size_t)B_ * NC * 2 * CE]; // hi/lo interleaved
__device__ __nv_bfloat16 g_vhl[(size_t)B_ * NC * 2 * CE]; // transposed, interleaved
__device__ __nv_bfloat16 g_yh[B_ * NQ * CE];              // attn out, d-permuted
__device__ __nv_bfloat16 g_yl[B_ * NQ * CE];

// ---------------------------------------------------------------------------
// helpers
// ---------------------------------------------------------------------------
#define MMA_BF16(d, a0, a1, a2, a3, b0, b1) \
    asm volatile("mma.sync.aligned.m16n8k16.row.col.f32.bf16.bf16.f32 " \
        "{%0,%1,%2,%3}, {%4,%5,%6,%7}, {%8,%9}, {%0,%1,%2,%3};" \
        : "+f"((d)[0]), "+f"((d)[1]), "+f"((d)[2]), "+f"((d)[3]) \
        : "r"(a0), "r"(a1), "r"(a2), "r"(a3), "r"(b0), "r"(b1))

#define CP16(dst, src) \
    asm volatile("cp.async.cg.shared.global [%0], [%1], 16;" \
                 :: "r"(dst), "l"(src))
#define CP_COMMIT() asm volatile("cp.async.commit_group;")

__device__ __forceinline__ uint32_t b2u(__nv_bfloat162 x) {
    return *reinterpret_cast<uint32_t*>(&x);
}
__device__ __forceinline__ uint32_t smem_u32(const void* p) {
    uint32_t a;
    asm("{ .reg .u64 t; cvta.to.shared.u64 t, %1; cvt.u32.u64 %0, t; }"
        : "=r"(a) : "l"(p));
    return a;
}

// ---------------------------------------------------------------------------
// Heat-kernel bias precompute -> fp16
// ---------------------------------------------------------------------------
__global__ __launch_bounds__(256)
void heat_precompute(const float* __restrict__ pos_c, const float* __restrict__ pos_q,
                     __half* __restrict__ heat) {
    const int b  = blockIdx.y;
    const int qi = blockIdx.x;
    const float* pq = pos_q + (size_t)(b * NQ + qi) * 3;
    const float qx = pq[0], qy = pq[1], qt = pq[2];
    __half2* hrow = (__half2*)(heat + ((size_t)b * NQ + qi) * NC);
    for (int c2 = threadIdx.x; c2 < NC / 2; c2 += 256) {
        const float* pc = pos_c + (size_t)(b * NC + c2 * 2) * 3;
        float dx0 = qx - pc[0], dy0 = qy - pc[1], dt0 = qt - pc[2];
        float dx1 = qx - pc[3], dy1 = qy - pc[4], dt1 = qt - pc[5];
        float e0 = __expf(-__fdividef(dx0 * dx0 + dy0 * dy0,
                                      FOURNU * fabsf(dt0) + EPS_));
        float e1 = __expf(-__fdividef(dx1 * dx1 + dy1 * dy1,
                                      FOURNU * fabsf(dt1) + EPS_));
        hrow[c2] = __floats2half2_rn(e0, e1);
    }
}

// ---------------------------------------------------------------------------
// bf16 hi/lo split body (k-pair-interleaved output)
// ---------------------------------------------------------------------------
__device__ __forceinline__ void split_body(const float* __restrict__ in,
                                           __nv_bfloat16* __restrict__ oh,
                                           __nv_bfloat16* __restrict__ ol, int i) {
    float4 v = ((const float4*)in)[i];
    __nv_bfloat162 hA = __floats2bfloat162_rn(v.x, v.y);
    __nv_bfloat162 hB = __floats2bfloat162_rn(v.z, v.w);
    __nv_bfloat162 lA = __floats2bfloat162_rn(v.x - __bfloat162float(hA.x),
                                              v.y - __bfloat162float(hA.y));
    __nv_bfloat162 lB = __floats2bfloat162_rn(v.z - __bfloat162float(hB.x),
                                              v.w - __bfloat162float(hB.y));
    size_t e = (size_t)i * 4;
    size_t base = e & ~(size_t)15;
    int lp0 = (int)(e & 15) >> 1;
    int s0 = (lp0 < 4) ? lp0 * 2 : (lp0 - 4) * 2 + 1;
    int lp1 = lp0 + 1;
    int s1 = (lp1 < 4) ? lp1 * 2 : (lp1 - 4) * 2 + 1;
    *(uint32_t*)&oh[base + s0 * 2] = b2u(hA);
    *(uint32_t*)&oh[base + s1 * 2] = b2u(hB);
    *(uint32_t*)&ol[base + s0 * 2] = b2u(lA);
    *(uint32_t*)&ol[base + s1 * 2] = b2u(lB);
}

__global__ __launch_bounds__(256)
void split_all(const float* __restrict__ xq, const float* __restrict__ xc,
               const float* __restrict__ w0, const float* __restrict__ w1,
               const float* __restrict__ w2, const float* __restrict__ w3,
               __nv_bfloat16* __restrict__ oqh, __nv_bfloat16* __restrict__ oql,
               __nv_bfloat16* __restrict__ och, __nv_bfloat16* __restrict__ ocl,
               __nv_bfloat16* __restrict__ owh, __nv_bfloat16* __restrict__ owl) {
    constexpr int NBQ = (B_ * NQ * CE) / 1024;
    constexpr int NBC = (B_ * NC * CE) / 1024;
    constexpr int NBW = (CE * CE) / 1024;
    int bid = blockIdx.x;
    if (bid < NBQ) {
        split_body(xq, oqh, oql, bid * 256 + threadIdx.x);
    } else if (bid < NBQ + NBC) {
        split_body(xc, och, ocl, (bid - NBQ) * 256 + threadIdx.x);
    } else {
        int wb = bid - NBQ - NBC;
        int j  = wb / NBW;
        const float* in = (j == 0) ? w0 : (j == 1) ? w1 : (j == 2) ? w2 : w3;
        size_t off = (size_t)j * CE * CE;
        split_body(in, owh + off, owl + off, (wb - j * NBW) * 256 + threadIdx.x);
    }
}

// ---------------------------------------------------------------------------
// Batched Q/K/V projection GEMM.  z=0: Q (separate hi/lo arrays, d-permuted,
// scaled).  z=1: K -> interleaved g_khl.  z=2: V -> transposed+interleaved
// g_vhl via smem.
// ---------------------------------------------------------------------------
constexpr int GEMM_SMEM_B = 73728;

__global__ __launch_bounds__(256, 2)
void proj_qkv(const __nv_bfloat16* __restrict__ xqh, const __nv_bfloat16* __restrict__ xql,
              const __nv_bfloat16* __restrict__ xch, const __nv_bfloat16* __restrict__ xcl,
              const __nv_bfloat16* __restrict__ wh,  const __nv_bfloat16* __restrict__ wl,
              const float* __restrict__ bq, const float* __restrict__ bk,
              const float* __restrict__ bv,
              __nv_bfloat16* __restrict__ qh, __nv_bfloat16* __restrict__ ql,
              __nv_bfloat16* __restrict__ khl, __nv_bfloat16* __restrict__ vhl) {
    const int z = blockIdx.z;
    const int nrows = (z == 0) ? 32 : 64;
    if (blockIdx.y >= nrows) return;

    const __nv_bfloat16* Ah = (z == 0) ? xqh : xch;
    const __nv_bfloat16* Al = (z == 0) ? xql : xcl;
    const __nv_bfloat16* Bh = wh + (size_t)z * CE * CE;
    const __nv_bfloat16* Bl = wl + (size_t)z * CE * CE;
    const float* bias = (z == 0) ? bq : (z == 1) ? bk : bv;

    extern __shared__ char gsm[];
    const uint32_t sb = smem_u32(gsm);

    const int tid  = threadIdx.x;
    const int lane = tid & 31;
    const int wid  = tid >> 5;
    const int grp  = lane >> 2;
    const int tig  = lane & 3;
    const int wm   = (wid >> 1) * 32;
    const int wn   = (wid & 1) * 32;
    const int rowBase = blockIdx.y * 128;
    const int colBase = blockIdx.x * 64;

    const int ar = tid >> 2;
    const int ac = tid & 3;

    auto issue = [&](uint32_t bb, int k0) {
        #pragma unroll
        for (int t = 0; t < 2; ++t) {
            int r = ar + t * 64;
            size_t src = (size_t)(rowBase + r) * 512 + k0 + ac * 8;
            uint32_t dst = bb + r * 96 + ac * 16;
            CP16(dst,         Ah + src);
            CP16(dst + 12288, Al + src);
        }
        {
            size_t src = (size_t)(colBase + ar) * 512 + k0 + ac * 8;
            uint32_t dst = bb + 24576 + ar * 96 + ac * 16;
            CP16(dst,        Bh + src);
            CP16(dst + 6144, Bl + src);
        }
        CP_COMMIT();
    };

    float acc[2][4][4];
    #pragma unroll
    for (int mt = 0; mt < 2; ++mt)
        #pragma unroll
        for (int nt = 0; nt < 4; ++nt)
            #pragma unroll
            for (int r = 0; r < 4; ++r) acc[mt][nt][r] = 0.f;

    issue(sb, 0);

    for (int c = 0; c < 16; ++c) {
        const int cur = c & 1;
        const char* bufc = gsm + cur * 36864;
        if (c < 15) issue(sb + (cur ^ 1) * 36864, (c + 1) * 32);
        if (c < 15) asm volatile("cp.async.wait_group 1;" ::: "memory");
        else        asm volatile("cp.async.wait_group 0;" ::: "memory");
        __syncthreads();

        #pragma unroll
        for (int sub = 0; sub < 2; ++sub) {
            const int kbyte = sub * 32 + tig * 8;
            uint32_t ah[2][4], al[2][4];
            #pragma unroll
            for (int mt = 0; mt < 2; ++mt) {
                int r0 = wm + mt * 16 + grp;
                uint2 h0 = *(const uint2*)(bufc + r0 * 96 + kbyte);
                uint2 h1 = *(const uint2*)(bufc + (r0 + 8) * 96 + kbyte);
                uint2 l0 = *(const uint2*)(bufc + 12288 + r0 * 96 + kbyte);
                uint2 l1 = *(const uint2*)(bufc + 12288 + (r0 + 8) * 96 + kbyte);
                ah[mt][0] = h0.x; ah[mt][1] = h1.x; ah[mt][2] = h0.y; ah[mt][3] = h1.y;
                al[mt][0] = l0.x; al[mt][1] = l1.x; al[mt][2] = l0.y; al[mt][3] = l1.y;
            }
            #pragma unroll
            for (int nt = 0; nt < 4; ++nt) {
                int n = wn + nt * 8 + grp;
                uint2 bh2 = *(const uint2*)(bufc + 24576 + n * 96 + kbyte);
                uint2 bl2 = *(const uint2*)(bufc + 30720 + n * 96 + kbyte);
                #pragma unroll
                for (int mt = 0; mt < 2; ++mt) {
                    MMA_BF16(acc[mt][nt], ah[mt][0], ah[mt][1], ah[mt][2], ah[mt][3],
                             bh2.x, bh2.y);
                    MMA_BF16(acc[mt][nt], ah[mt][0], ah[mt][1], ah[mt][2], ah[mt][3],
                             bl2.x, bl2.y);
                    MMA_BF16(acc[mt][nt], al[mt][0], al[mt][1], al[mt][2], al[mt][3],
                             bh2.x, bh2.y);
                }
            }
        }
        __syncthreads();
    }

    if (z == 0) {
        // ---- Q epilogue: separate hi/lo, k-permuted, scaled ----
        #pragma unroll
        for (int nt = 0; nt < 4; ++nt) {
            int col = colBase + wn + nt * 8 + tig * 2;
            float b0 = __ldg(&bias[col]);
            float b1 = __ldg(&bias[col + 1]);
            int colp = (col & ~15) + perm16(col & 15);
            #pragma unroll
            for (int mt = 0; mt < 2; ++mt) {
                int row = rowBase + wm + mt * 16 + grp;
                float v00 = (acc[mt][nt][0] + b0) * SCALE;
                float v01 = (acc[mt][nt][1] + b1) * SCALE;
                float v10 = (acc[mt][nt][2] + b0) * SCALE;
                float v11 = (acc[mt][nt][3] + b1) * SCALE;
                __nv_bfloat162 h0 = __floats2bfloat162_rn(v00, v01);
                __nv_bfloat162 h1 = __floats2bfloat162_rn(v10, v11);
                __nv_bfloat162 l0 = __floats2bfloat162_rn(v00 - __bfloat162float(h0.x),
                                                          v01 - __bfloat162float(h0.y));
                __nv_bfloat162 l1 = __floats2bfloat162_rn(v10 - __bfloat162float(h1.x),
                                                          v11 - __bfloat162float(h1.y));
                *(uint32_t*)&qh[(size_t)row       * 512 + colp] = b2u(h0);
                *(uint32_t*)&qh[(size_t)(row + 8) * 512 + colp] = b2u(h1);
                *(uint32_t*)&ql[(size_t)row       * 512 + colp] = b2u(l0);
                *(uint32_t*)&ql[(size_t)(row + 8) * 512 + colp] = b2u(l1);
            }
        }
    } else if (z == 1) {
        // ---- K epilogue: interleaved hi/lo blocks ----
        #pragma unroll
        for (int nt = 0; nt < 4; ++nt) {
            int col = colBase + wn + nt * 8 + tig * 2;
            float b0 = __ldg(&bias[col]);
            float b1 = __ldg(&bias[col + 1]);
            int head = col >> 6;
            int dl   = col & 63;
            int s0i  = perm16(dl & 15);                       // even slot
            int eoff = head * 128 + (dl >> 4) * 32 + (s0i >> 2) * 8 + (s0i & 3);
            #pragma unroll
            for (int mt = 0; mt < 2; ++mt) {
                int row = rowBase + wm + mt * 16 + grp;
                float v00 = acc[mt][nt][0] + b0, v01 = acc[mt][nt][1] + b1;
                float v10 = acc[mt][nt][2] + b0, v11 = acc[mt][nt][3] + b1;
                __nv_bfloat162 h0 = __floats2bfloat162_rn(v00, v01);
                __nv_bfloat162 h1 = __floats2bfloat162_rn(v10, v11);
                __nv_bfloat162 l0 = __floats2bfloat162_rn(v00 - __bfloat162float(h0.x),
                                                          v01 - __bfloat162float(h0.y));
                __nv_bfloat162 l1 = __floats2bfloat162_rn(v10 - __bfloat162float(h1.x),
                                                          v11 - __bfloat162float(h1.y));
                *(uint32_t*)&khl[(size_t)row       * 1024 + eoff]     = b2u(h0);
                *(uint32_t*)&khl[(size_t)(row + 8) * 1024 + eoff]     = b2u(h1);
                *(uint32_t*)&khl[(size_t)row       * 1024 + eoff + 4] = b2u(l0);
                *(uint32_t*)&khl[(size_t)(row + 8) * 1024 + eoff + 4] = b2u(l1);
            }
        }
    } else {
        // ---- V epilogue: smem transpose -> [b][h][d][c interleaved] ----
        constexpr int ST = 132;
        __nv_bfloat16* tsh = (__nv_bfloat16*)gsm;
        __nv_bfloat16* tsl = tsh + 64 * ST;
        __syncthreads();
        #pragma unroll
        for (int nt = 0; nt < 4; ++nt) {
            int dl = wn + nt * 8 + tig * 2;
            float b0 = __ldg(&bias[colBase + dl]);
            float b1 = __ldg(&bias[colBase + dl + 1]);
            #pragma unroll
            for (int mt = 0; mt < 2; ++mt) {
                int rl = wm + mt * 16 + grp;
                float v00 = acc[mt][nt][0] + b0, v01 = acc[mt][nt][1] + b1;
                float v10 = acc[mt][nt][2] + b0, v11 = acc[mt][nt][3] + b1;
                __nv_bfloat16 h00 = __float2bfloat16_rn(v00);
                __nv_bfloat16 h01 = __float2bfloat16_rn(v01);
                __nv_bfloat16 h10 = __float2bfloat16_rn(v10);
                __nv_bfloat16 h11 = __float2bfloat16_rn(v11);
                tsh[(dl)     * ST + rl]     = h00;
                tsh[(dl + 1) * ST + rl]     = h01;
                tsh[(dl)     * ST + rl + 8] = h10;
                tsh[(dl + 1) * ST + rl + 8] = h11;
                tsl[(dl)     * ST + rl]     = __float2bfloat16_rn(v00 - __bfloat162float(h00));
                tsl[(dl + 1) * ST + rl]     = __float2bfloat16_rn(v01 - __bfloat162float(h01));
                tsl[(dl)     * ST + rl + 8] = __float2bfloat16_rn(v10 - __bfloat162float(h10));
                tsl[(dl + 1) * ST + rl + 8] = __float2bfloat16_rn(v11 - __bfloat162float(h11));
            }
        }
        __syncthreads();
        const int bb = rowBase >> 12;
        const int c0 = rowBase & 4095;
        const int hh = blockIdx.x;
        #pragma unroll
        for (int t = 0; t < 16; ++t) {
            int u  = tid + t * 256;
            int d  = u >> 6;
            int cl = (u & 63) * 2;
            uint32_t val_h = *(uint32_t*)&tsh[d * ST + cl];
            uint32_t val_l = *(uint32_t*)&tsl[d * ST + cl];
            int s0i = perm16(cl & 15);
            size_t rb = ((size_t)(bb * H_ + hh) * 64 + d) * (size_t)(NC * 2);
            int off = (c0 + (cl & ~15)) * 2 + (s0i >> 2) * 8 + (s0i & 3);
            *(uint32_t*)&vhl[rb + off]     = val_h;
            *(uint32_t*)&vhl[rb + off + 4] = val_l;
        }
    }
}

// ---------------------------------------------------------------------------
// O-projection GEMM (fp32 out).
// ---------------------------------------------------------------------------
__global__ __launch_bounds__(256, 2)
void gemm_o(const __nv_bfloat16* __restrict__ Ah, const __nv_bfloat16* __restrict__ Al,
            const __nv_bfloat16* __restrict__ Bh, const __nv_bfloat16* __restrict__ Bl,
            const float* __restrict__ bias, float* __restrict__ Yf) {
    extern __shared__ char gsm[];
    const uint32_t sb = smem_u32(gsm);

    const int tid  = threadIdx.x;
    const int lane = tid & 31;
    const int wid  = tid >> 5;
    const int grp  = lane >> 2;
    const int tig  = lane & 3;
    const int wm   = (wid >> 1) * 32;
    const int wn   = (wid & 1) * 32;
    const int rowBase = blockIdx.y * 128;
    const int colBase = blockIdx.x * 64;

    const int ar = tid >> 2;
    const int ac = tid & 3;

    auto issue = [&](uint32_t bb, int k0) {
        #pragma unroll
        for (int t = 0; t < 2; ++t) {
            int r = ar + t * 64;
            size_t src = (size_t)(rowBase + r) * 512 + k0 + ac * 8;
            uint32_t dst = bb + r * 96 + ac * 16;
            CP16(dst,         Ah + src);
            CP16(dst + 12288, Al + src);
        }
        {
            size_t src = (size_t)(colBase + ar) * 512 + k0 + ac * 8;
            uint32_t dst = bb + 24576 + ar * 96 + ac * 16;
            CP16(dst,        Bh + src);
            CP16(dst + 6144, Bl + src);
        }
        CP_COMMIT();
    };

    float acc[2][4][4];
    #pragma unroll
    for (int mt = 0; mt < 2; ++mt)
        #pragma unroll
        for (int nt = 0; nt < 4; ++nt)
            #pragma unroll
            for (int r = 0; r < 4; ++r) acc[mt][nt][r] = 0.f;

    issue(sb, 0);

    for (int c = 0; c < 16; ++c) {
        const int cur = c & 1;
        const char* bufc = gsm + cur * 36864;
        if (c < 15) issue(sb + (cur ^ 1) * 36864, (c + 1) * 32);
        if (c < 15) asm volatile("cp.async.wait_group 1;" ::: "memory");
        else        asm volatile("cp.async.wait_group 0;" ::: "memory");
        __syncthreads();

        #pragma unroll
        for (int sub = 0; sub < 2; ++sub) {
            const int kbyte = sub * 32 + tig * 8;
            uint32_t ah[2][4], al[2][4];
            #pragma unroll
            for (int mt = 0; mt < 2; ++mt) {
                int r0 = wm + mt * 16 + grp;
                uint2 h0 = *(const uint2*)(bufc + r0 * 96 + kbyte);
                uint2 h1 = *(const uint2*)(bufc + (r0 + 8) * 96 + kbyte);
                uint2 l0 = *(const uint2*)(bufc + 12288 + r0 * 96 + kbyte);
                uint2 l1 = *(const uint2*)(bufc + 12288 + (r0 + 8) * 96 + kbyte);
                ah[mt][0] = h0.x; ah[mt][1] = h1.x; ah[mt][2] = h0.y; ah[mt][3] = h1.y;
                al[mt][0] = l0.x; al[mt][1] = l1.x; al[mt][2] = l0.y; al[mt][3] = l1.y;
            }
            #pragma unroll
            for (int nt = 0; nt < 4; ++nt) {
                int n = wn + nt * 8 + grp;
                uint2 bh2 = *(const uint2*)(bufc + 24576 + n * 96 + kbyte);
                uint2 bl2 = *(const uint2*)(bufc + 30720 + n * 96 + kbyte);
                #pragma unroll
                for (int mt = 0; mt < 2; ++mt) {
                    MMA_BF16(acc[mt][nt], ah[mt][0], ah[mt][1], ah[mt][2], ah[mt][3],
                             bh2.x, bh2.y);
                    MMA_BF16(acc[mt][nt], ah[mt][0], ah[mt][1], ah[mt][2], ah[mt][3],
                             bl2.x, bl2.y);
                    MMA_BF16(acc[mt][nt], al[mt][0], al[mt][1], al[mt][2], al[mt][3],
                             bh2.x, bh2.y);
                }
            }
        }
        __syncthreads();
    }

    #pragma unroll
    for (int nt = 0; nt < 4; ++nt) {
        int col = colBase + wn + nt * 8 + tig * 2;
        float b0 = __ldg(&bias[col]);
        float b1 = __ldg(&bias[col + 1]);
        #pragma unroll
        for (int mt = 0; mt < 2; ++mt) {
            int row = rowBase + wm + mt * 16 + grp;
            *(float2*)&Yf[(size_t)row       * 512 + col] =
                make_float2(acc[mt][nt][0] + b0, acc[mt][nt][1] + b1);
            *(float2*)&Yf[(size_t)(row + 8) * 512 + col] =
                make_float2(acc[mt][nt][2] + b0, acc[mt][nt][3] + b1);
        }
    }
}

// ---------------------------------------------------------------------------
// Tensor-core flash attention v5: interleaved hi/lo K/V tiles (LDS.128 frags,
// stride 320 conflict-free), pipelined chunks, fp16 heat.
// Smem: buf[2] of 40960  {K 0..20480 | V 20480..40960}.  Total 81920.
// ---------------------------------------------------------------------------
constexpr int ATTN_SMEM_B = 81920;

__global__ __launch_bounds__(256, 2)
void attn_tc(const __nv_bfloat16* __restrict__ qh, const __nv_bfloat16* __restrict__ ql,
             const __nv_bfloat16* __restrict__ khl, const __nv_bfloat16* __restrict__ vhl,
             const __half* __restrict__ heat,
             __nv_bfloat16* __restrict__ yh, __nv_bfloat16* __restrict__ yl) {
    extern __shared__ char smem[];
    const uint32_t sb = smem_u32(smem);

    const int b   = blockIdx.z;
    const int h   = blockIdx.y;
    const int q0  = blockIdx.x * 128;
    const int tid = threadIdx.x;
    const int w    = tid >> 5;
    const int lane = tid & 31;
    const int grp  = lane >> 2;
    const int tig  = lane & 3;

    const int sr  = tid >> 2;          // 0..63 row
    const int sc4 = (tid & 3) * 4;     // chunk base (4 chunks of 16B per thread)

    const char* kbase = (const char*)khl;
    const char* vbase = (const char*)vhl;

    auto issue_tile = [&](uint32_t bb, int c0) {
        size_t ksrc = (size_t)(b * NC + c0 + sr) * 2048 + h * 256;
        size_t vsrc = ((size_t)(b * H_ + h) * 64 + sr) * (size_t)(NC * 4) + (size_t)c0 * 4;
        uint32_t kd = bb + sr * 320;
        uint32_t vd = bb + 20480 + sr * 320;
        #pragma unroll
        for (int j = 0; j < 4; ++j) {
            int ch = sc4 + j;
            CP16(kd + ch * 16, kbase + ksrc + ch * 16);
            CP16(vd + ch * 16, vbase + vsrc + ch * 16);
        }
        CP_COMMIT();
    };

    const int qrow0 = b * NQ + q0 + w * 16 + grp;
    uint32_t qfh[4][4], qfl[4][4];
    #pragma unroll
    for (int ks = 0; ks < 4; ++ks) {
        size_t e0 = (size_t)qrow0 * 512 + h * 64 + ks * 16 + tig * 4;
        size_t e1 = e0 + (size_t)8 * 512;
        uint2 h0 = *(const uint2*)(qh + e0);
        uint2 h1 = *(const uint2*)(qh + e1);
        uint2 l0v = *(const uint2*)(ql + e0);
        uint2 l1v = *(const uint2*)(ql + e1);
        qfh[ks][0] = h0.x; qfh[ks][1] = h1.x; qfh[ks][2] = h0.y; qfh[ks][3] = h1.y;
        qfl[ks][0] = l0v.x; qfl[ks][1] = l1v.x; qfl[ks][2] = l0v.y; qfl[ks][3] = l1v.y;
    }

    float acc[8][4];
    #pragma unroll
    for (int m = 0; m < 8; ++m)
        #pragma unroll
        for (int r = 0; r < 4; ++r) acc[m][r] = 0.f;
    float lq0 = 0.f, lq8 = 0.f;

    const __half* hb0 = heat + (size_t)qrow0 * NC;
    const __half* hb1 = hb0 + (size_t)8 * NC;

    auto qk_chunk = [&](const char* bufc, int kc, float* s0, float* s1) {
        #pragma unroll
        for (int ks = 0; ks < 4; ++ks) {
            int r0 = (kc * 16 + grp) * 320 + ks * 64 + tig * 16;
            uint4 k0 = *(const uint4*)(bufc + r0);
            uint4 k1 = *(const uint4*)(bufc + r0 + 8 * 320);
            MMA_BF16(s0, qfh[ks][0], qfh[ks][1], qfh[ks][2], qfh[ks][3], k0.x, k0.y);
            MMA_BF16(s0, qfh[ks][0], qfh[ks][1], qfh[ks][2], qfh[ks][3], k0.z, k0.w);
            MMA_BF16(s0, qfl[ks][0], qfl[ks][1], qfl[ks][2], qfl[ks][3], k0.x, k0.y);
            MMA_BF16(s1, qfh[ks][0], qfh[ks][1], qfh[ks][2], qfh[ks][3], k1.x, k1.y);
            MMA_BF16(s1, qfh[ks][0], qfh[ks][1], qfh[ks][2], qfh[ks][3], k1.z, k1.w);
            MMA_BF16(s1, qfl[ks][0], qfl[ks][1], qfl[ks][2], qfl[ks][3], k1.x, k1.y);
        }
    };

    issue_tile(sb, 0);

    for (int it = 0; it < 64; ++it) {
        const int cur = it & 1;
        const char* bufc = smem + cur * 40960;
        if (it < 63) issue_tile(sb + (cur ^ 1) * 40960, (it + 1) * 64);
        if (it < 63) asm volatile("cp.async.wait_group 1;" ::: "memory");
        else         asm volatile("cp.async.wait_group 0;" ::: "memory");
        __syncthreads();

        const int c0 = it * 64;
        uint32_t HA0 = *(const uint32_t*)(hb0 + c0 + tig * 2);
        uint32_t HA1 = *(const uint32_t*)(hb1 + c0 + tig * 2);
        uint32_t HB0 = *(const uint32_t*)(hb0 + c0 + 8 + tig * 2);
        uint32_t HB1 = *(const uint32_t*)(hb1 + c0 + 8 + tig * 2);

        float s0[4] = {0.f, 0.f, 0.f, 0.f};
        float s1[4] = {0.f, 0.f, 0.f, 0.f};
        qk_chunk(bufc, 0, s0, s1);

        #pragma unroll
        for (int kc = 0; kc < 4; ++kc) {
            float2 ha0 = __half22float2(*(const __half2*)&HA0);
            float2 ha1 = __half22float2(*(const __half2*)&HA1);
            float2 hc0 = __half22float2(*(const __half2*)&HB0);
            float2 hc1 = __half22float2(*(const __half2*)&HB1);
            if (kc < 3) {
                int nb = c0 + (kc + 1) * 16 + tig * 2;
                HA0 = *(const uint32_t*)(hb0 + nb);
                HA1 = *(const uint32_t*)(hb1 + nb);
                HB0 = *(const uint32_t*)(hb0 + nb + 8);
                HB1 = *(const uint32_t*)(hb1 + nb + 8);
            }

            float e00 = __expf(s0[0] + ha0.x);
            float e01 = __expf(s0[1] + ha0.y);
            float e10 = __expf(s0[2] + ha1.x);
            float e11 = __expf(s0[3] + ha1.y);
            lq0 += e00 + e01;
            lq8 += e10 + e11;
            __nv_bfloat162 p0 = __floats2bfloat162_rn(e00, e01);
            __nv_bfloat162 p1 = __floats2bfloat162_rn(e10, e11);
            __nv_bfloat162 r0v = __floats2bfloat162_rn(e00 - __bfloat162float(p0.x),
                                                       e01 - __bfloat162float(p0.y));
            __nv_bfloat162 r1v = __floats2bfloat162_rn(e10 - __bfloat162float(p1.x),
                                                       e11 - __bfloat162float(p1.y));
            float f00 = __expf(s1[0] + hc0.x);
            float f01 = __expf(s1[1] + hc0.y);
            float f10 = __expf(s1[2] + hc1.x);
            float f11 = __expf(s1[3] + hc1.y);
            lq0 += f00 + f01;
            lq8 += f10 + f11;
            __nv_bfloat162 p2 = __floats2bfloat162_rn(f00, f01);
            __nv_bfloat162 p3 = __floats2bfloat162_rn(f10, f11);
            __nv_bfloat162 r2v = __floats2bfloat162_rn(f00 - __bfloat162float(p2.x),
                                                       f01 - __bfloat162float(p2.y));
            __nv_bfloat162 r3v = __floats2bfloat162_rn(f10 - __bfloat162float(p3.x),
                                                       f11 - __bfloat162float(p3.y));
            uint32_t a0 = b2u(p0), a1 = b2u(p1), a2 = b2u(p2), a3 = b2u(p3);
            uint32_t c0r = b2u(r0v), c1r = b2u(r1v), c2r = b2u(r2v), c3r = b2u(r3v);

            float t0[4] = {0.f, 0.f, 0.f, 0.f};
            float t1[4] = {0.f, 0.f, 0.f, 0.f};
            if (kc < 3) qk_chunk(bufc, kc + 1, t0, t1);

            #pragma unroll
            for (int m = 0; m < 8; ++m) {
                int boff = 20480 + (m * 8 + grp) * 320 + kc * 64 + tig * 16;
                uint4 v = *(const uint4*)(bufc + boff);
                MMA_BF16(acc[m], a0, a1, a2, a3, v.x, v.y);
                MMA_BF16(acc[m], a0, a1, a2, a3, v.z, v.w);
                MMA_BF16(acc[m], c0r, c1r, c2r, c3r, v.x, v.y);
            }

            #pragma unroll
            for (int r = 0; r < 4; ++r) { s0[r] = t0[r]; s1[r] = t1[r]; }
        }
        __syncthreads();
    }

    lq0 += __shfl_xor_sync(0xffffffffu, lq0, 1);
    lq0 += __shfl_xor_sync(0xffffffffu, lq0, 2);
    lq8 += __shfl_xor_sync(0xffffffffu, lq8, 1);
    lq8 += __shfl_xor_sync(0xffffffffu, lq8, 2);
    float i0 = 1.0f / lq0;
    float i1 = 1.0f / lq8;

    size_t yr0 = (size_t)qrow0 * 512 + h * 64;
    size_t yr1 = yr0 + (size_t)8 * 512;
    #pragma unroll
    for (int nt = 0; nt < 8; ++nt) {
        int ccp = (nt >> 1) * 16 + (nt & 1) * 2 + tig * 4;   // d-permuted
        float v00 = acc[nt][0] * i0, v01 = acc[nt][1] * i0;
        float v10 = acc[nt][2] * i1, v11 = acc[nt][3] * i1;
        __nv_bfloat162 h0 = __floats2bfloat162_rn(v00, v01);
        __nv_bfloat162 h1 = __floats2bfloat162_rn(v10, v11);
        __nv_bfloat162 l0v = __floats2bfloat162_rn(v00 - __bfloat162float(h0.x),
                                                   v01 - __bfloat162float(h0.y));
        __nv_bfloat162 l1v = __floats2bfloat162_rn(v10 - __bfloat162float(h1.x),
                                                   v11 - __bfloat162float(h1.y));
        *(uint32_t*)&yh[yr0 + ccp] = b2u(h0);
        *(uint32_t*)&yh[yr1 + ccp] = b2u(h1);
        *(uint32_t*)&yl[yr0 + ccp] = b2u(l0v);
        *(uint32_t*)&yl[yr1 + ccp] = b2u(l1v);
    }
}

// ---------------------------------------------------------------------------
// Launch (attn_tc at index 3 for ncu).
// ---------------------------------------------------------------------------
extern "C" void kernel_launch(void* const* d_in, const int* in_sizes, int n_in,
                              void* d_out, int out_size) {
    (void)in_sizes; (void)n_in; (void)out_size;
    const float* x_ctx     = (const float*)d_in[0];
    const float* x_query   = (const float*)d_in[1];
    const float* pos_ctx   = (const float*)d_in[2];
    const float* pos_query = (const float*)d_in[3];
    const float* Wq = (const float*)d_in[4];
    const float* bq = (const float*)d_in[5];
    const float* Wk = (const float*)d_in[6];
    const float* bk = (const float*)d_in[7];
    const float* Wv = (const float*)d_in[8];
    const float* bv = (const float*)d_in[9];
    const float* Wo = (const float*)d_in[10];
    const float* bo = (const float*)d_in[11];
    float* out = (float*)d_out;

    __half* gh;
    __nv_bfloat16 *gxqh, *gxql, *gxch, *gxcl, *gwh, *gwl;
    __nv_bfloat16 *gqh, *gql, *gkhl, *gvhl, *gyh, *gyl;
    cudaGetSymbolAddress((void**)&gh,   g_heat);
    cudaGetSymbolAddress((void**)&gxqh, g_xqh);
    cudaGetSymbolAddress((void**)&gxql, g_xql);
    cudaGetSymbolAddress((void**)&gxch, g_xch);
    cudaGetSymbolAddress((void**)&gxcl, g_xcl);
    cudaGetSymbolAddress((void**)&gwh,  g_wh);
    cudaGetSymbolAddress((void**)&gwl,  g_wl);
    cudaGetSymbolAddress((void**)&gqh,  g_qh);
    cudaGetSymbolAddress((void**)&gql,  g_ql);
    cudaGetSymbolAddress((void**)&gkhl, g_khl);
    cudaGetSymbolAddress((void**)&gvhl, g_vhl);
    cudaGetSymbolAddress((void**)&gyh,  g_yh);
    cudaGetSymbolAddress((void**)&gyl,  g_yl);

    cudaFuncSetAttribute(attn_tc,
                         cudaFuncAttributeMaxDynamicSharedMemorySize, ATTN_SMEM_B);
    cudaFuncSetAttribute(proj_qkv,
                         cudaFuncAttributeMaxDynamicSharedMemorySize, GEMM_SMEM_B);
    cudaFuncSetAttribute(gemm_o,
                         cudaFuncAttributeMaxDynamicSharedMemorySize, GEMM_SMEM_B);

    // launch 0
    split_all<<<(B_ * NQ * CE + B_ * NC * CE) / 1024 + 4 * (CE * CE) / 1024, 256>>>(
        x_query, x_ctx, Wq, Wk, Wv, Wo, gxqh, gxql, gxch, gxcl, gwh, gwl);
    // launch 1
    heat_precompute<<<dim3(NQ, B_), 256>>>(pos_ctx, pos_query, gh);
    // launch 2
    proj_qkv<<<dim3(8, 64, 3), 256, GEMM_SMEM_B>>>(
        gxqh, gxql, gxch, gxcl, gwh, gwl, bq, bk, bv,
        gqh, gql, gkhl, gvhl);
    // launch 3: attention (profiled)
    attn_tc<<<dim3(NQ / 128, H_, B_), 256, ATTN_SMEM_B>>>(
        gqh, gql, gkhl, gvhl, gh, gyh, gyl);
    // launch 4
    gemm_o<<<dim3(8, (B_ * NQ) / 128), 256, GEMM_SMEM_B>>>(
        gyh, gyl, gwh + 3 * CE * CE, gwl + 3 * CE * CE, bo, out);
}

// round 15
// speedup vs baseline: 1.2219x; 1.2219x over previous
#include <cuda_runtime.h>
#include <cuda_bf16.h>
#include <cuda_fp16.h>
#include <cstdint>
#include <math.h>

// ---------------------------------------------------------------------------
// Problem constants
// ---------------------------------------------------------------------------
constexpr int B_  = 2;
constexpr int NQ  = 2048;
constexpr int NC  = 4096;
constexpr int CE  = 512;
constexpr int H_  = 8;
constexpr float SCALE  = 0.125f;
constexpr float FOURNU = 0.4f;
constexpr float EPS_   = 1e-6f;

// Pair-interleave permutation within a 16-element k-chunk (validated R7+).
__host__ __device__ constexpr int perm16(int e) {
    int lp = e >> 1, o = e & 1;
    int slot = (lp < 4) ? (lp * 2) : ((lp - 4) * 2 + 1);
    return slot * 2 + o;
}

// ---------------------------------------------------------------------------
// Scratch (R11 layouts: separate hi/lo arrays; V transposed per head, fp16)
// ---------------------------------------------------------------------------
__device__ __half g_heat[(size_t)B_ * NQ * NC];           // 33.5 MB (fp16)
__device__ __nv_bfloat16 g_xqh[B_ * NQ * CE];
__device__ __nv_bfloat16 g_xql[B_ * NQ * CE];
__device__ __nv_bfloat16 g_xch[B_ * NC * CE];
__device__ __nv_bfloat16 g_xcl[B_ * NC * CE];
__device__ __nv_bfloat16 g_wh[4 * CE * CE];
__device__ __nv_bfloat16 g_wl[4 * CE * CE];
__device__ __nv_bfloat16 g_qh[B_ * NQ * CE];              // scaled, d-permuted
__device__ __nv_bfloat16 g_ql[B_ * NQ * CE];
__device__ __nv_bfloat16 g_kh[B_ * NC * CE];              // d-permuted
__device__ __nv_bfloat16 g_kl[B_ * NC * CE];
__device__ __half g_vth[B_ * NC * CE];                    // [b][h][d][c], c-permuted, fp16 hi
__device__ __half g_vtl[B_ * NC * CE];                    // fp16 lo
__device__ __nv_bfloat16 g_yh[B_ * NQ * CE];              // attn out, d-permuted
__device__ __nv_bfloat16 g_yl[B_ * NQ * CE];

// ---------------------------------------------------------------------------
// helpers
// ---------------------------------------------------------------------------
#define MMA_BF16(d, a0, a1, a2, a3, b0, b1) \
    asm volatile("mma.sync.aligned.m16n8k16.row.col.f32.bf16.bf16.f32 " \
        "{%0,%1,%2,%3}, {%4,%5,%6,%7}, {%8,%9}, {%0,%1,%2,%3};" \
        : "+f"((d)[0]), "+f"((d)[1]), "+f"((d)[2]), "+f"((d)[3]) \
        : "r"(a0), "r"(a1), "r"(a2), "r"(a3), "r"(b0), "r"(b1))

#define MMA_F16(d, a0, a1, a2, a3, b0, b1) \
    asm volatile("mma.sync.aligned.m16n8k16.row.col.f32.f16.f16.f32 " \
        "{%0,%1,%2,%3}, {%4,%5,%6,%7}, {%8,%9}, {%0,%1,%2,%3};" \
        : "+f"((d)[0]), "+f"((d)[1]), "+f"((d)[2]), "+f"((d)[3]) \
        : "r"(a0), "r"(a1), "r"(a2), "r"(a3), "r"(b0), "r"(b1))

#define CP16(dst, src) \
    asm volatile("cp.async.cg.shared.global [%0], [%1], 16;" \
                 :: "r"(dst), "l"(src))
#define CP_COMMIT() asm volatile("cp.async.commit_group;")

__device__ __forceinline__ uint32_t b2u(__nv_bfloat162 x) {
    return *reinterpret_cast<uint32_t*>(&x);
}
__device__ __forceinline__ uint32_t h2u(__half2 x) {
    return *reinterpret_cast<uint32_t*>(&x);
}
__device__ __forceinline__ uint32_t smem_u32(const void* p) {
    uint32_t a;
    asm("{ .reg .u64 t; cvta.to.shared.u64 t, %1; cvt.u32.u64 %0, t; }"
        : "=r"(a) : "l"(p));
    return a;
}

// ---------------------------------------------------------------------------
// Heat-kernel bias precompute -> fp16
// ---------------------------------------------------------------------------
__global__ __launch_bounds__(256)
void heat_precompute(const float* __restrict__ pos_c, const float* __restrict__ pos_q,
                     __half* __restrict__ heat) {
    const int b  = blockIdx.y;
    const int qi = blockIdx.x;
    const float* pq = pos_q + (size_t)(b * NQ + qi) * 3;
    const float qx = pq[0], qy = pq[1], qt = pq[2];
    __half2* hrow = (__half2*)(heat + ((size_t)b * NQ + qi) * NC);
    for (int c2 = threadIdx.x; c2 < NC / 2; c2 += 256) {
        const float* pc = pos_c + (size_t)(b * NC + c2 * 2) * 3;
        float dx0 = qx - pc[0], dy0 = qy - pc[1], dt0 = qt - pc[2];
        float dx1 = qx - pc[3], dy1 = qy - pc[4], dt1 = qt - pc[5];
        float e0 = __expf(-__fdividef(dx0 * dx0 + dy0 * dy0,
                                      FOURNU * fabsf(dt0) + EPS_));
        float e1 = __expf(-__fdividef(dx1 * dx1 + dy1 * dy1,
                                      FOURNU * fabsf(dt1) + EPS_));
        hrow[c2] = __floats2half2_rn(e0, e1);
    }
}

// ---------------------------------------------------------------------------
// bf16 hi/lo split body (k-pair-interleaved output)
// ---------------------------------------------------------------------------
__device__ __forceinline__ void split_body(const float* __restrict__ in,
                                           __nv_bfloat16* __restrict__ oh,
                                           __nv_bfloat16* __restrict__ ol, int i) {
    float4 v = ((const float4*)in)[i];
    __nv_bfloat162 hA = __floats2bfloat162_rn(v.x, v.y);
    __nv_bfloat162 hB = __floats2bfloat162_rn(v.z, v.w);
    __nv_bfloat162 lA = __floats2bfloat162_rn(v.x - __bfloat162float(hA.x),
                                              v.y - __bfloat162float(hA.y));
    __nv_bfloat162 lB = __floats2bfloat162_rn(v.z - __bfloat162float(hB.x),
                                              v.w - __bfloat162float(hB.y));
    size_t e = (size_t)i * 4;
    size_t base = e & ~(size_t)15;
    int lp0 = (int)(e & 15) >> 1;
    int s0 = (lp0 < 4) ? lp0 * 2 : (lp0 - 4) * 2 + 1;
    int lp1 = lp0 + 1;
    int s1 = (lp1 < 4) ? lp1 * 2 : (lp1 - 4) * 2 + 1;
    *(uint32_t*)&oh[base + s0 * 2] = b2u(hA);
    *(uint32_t*)&oh[base + s1 * 2] = b2u(hB);
    *(uint32_t*)&ol[base + s0 * 2] = b2u(lA);
    *(uint32_t*)&ol[base + s1 * 2] = b2u(lB);
}

__global__ __launch_bounds__(256)
void split_all(const float* __restrict__ xq, const float* __restrict__ xc,
               const float* __restrict__ w0, const float* __restrict__ w1,
               const float* __restrict__ w2, const float* __restrict__ w3,
               __nv_bfloat16* __restrict__ oqh, __nv_bfloat16* __restrict__ oql,
               __nv_bfloat16* __restrict__ och, __nv_bfloat16* __restrict__ ocl,
               __nv_bfloat16* __restrict__ owh, __nv_bfloat16* __restrict__ owl) {
    constexpr int NBQ = (B_ * NQ * CE) / 1024;
    constexpr int NBC = (B_ * NC * CE) / 1024;
    constexpr int NBW = (CE * CE) / 1024;
    int bid = blockIdx.x;
    if (bid < NBQ) {
        split_body(xq, oqh, oql, bid * 256 + threadIdx.x);
    } else if (bid < NBQ + NBC) {
        split_body(xc, och, ocl, (bid - NBQ) * 256 + threadIdx.x);
    } else {
        int wb = bid - NBQ - NBC;
        int j  = wb / NBW;
        const float* in = (j == 0) ? w0 : (j == 1) ? w1 : (j == 2) ? w2 : w3;
        size_t off = (size_t)j * CE * CE;
        split_body(in, owh + off, owl + off, (wb - j * NBW) * 256 + threadIdx.x);
    }
}

// ---------------------------------------------------------------------------
// Batched Q/K/V projection GEMM.  z=0: Q, z=1: K (both bf16 hi/lo, permuted).
// z=2: V -> per-head transpose, fp16 hi/lo, c-permuted.
// ---------------------------------------------------------------------------
constexpr int GEMM_SMEM_B = 73728;

__global__ __launch_bounds__(256, 2)
void proj_qkv(const __nv_bfloat16* __restrict__ xqh, const __nv_bfloat16* __restrict__ xql,
              const __nv_bfloat16* __restrict__ xch, const __nv_bfloat16* __restrict__ xcl,
              const __nv_bfloat16* __restrict__ wh,  const __nv_bfloat16* __restrict__ wl,
              const float* __restrict__ bq, const float* __restrict__ bk,
              const float* __restrict__ bv,
              __nv_bfloat16* __restrict__ qh, __nv_bfloat16* __restrict__ ql,
              __nv_bfloat16* __restrict__ kh, __nv_bfloat16* __restrict__ kl,
              __half* __restrict__ vth, __half* __restrict__ vtl) {
    const int z = blockIdx.z;
    const int nrows = (z == 0) ? 32 : 64;
    if (blockIdx.y >= nrows) return;

    const __nv_bfloat16* Ah = (z == 0) ? xqh : xch;
    const __nv_bfloat16* Al = (z == 0) ? xql : xcl;
    const __nv_bfloat16* Bh = wh + (size_t)z * CE * CE;
    const __nv_bfloat16* Bl = wl + (size_t)z * CE * CE;
    const float* bias = (z == 0) ? bq : (z == 1) ? bk : bv;

    extern __shared__ char gsm[];
    const uint32_t sb = smem_u32(gsm);

    const int tid  = threadIdx.x;
    const int lane = tid & 31;
    const int wid  = tid >> 5;
    const int grp  = lane >> 2;
    const int tig  = lane & 3;
    const int wm   = (wid >> 1) * 32;
    const int wn   = (wid & 1) * 32;
    const int rowBase = blockIdx.y * 128;
    const int colBase = blockIdx.x * 64;

    const int ar = tid >> 2;
    const int ac = tid & 3;

    auto issue = [&](uint32_t bb, int k0) {
        #pragma unroll
        for (int t = 0; t < 2; ++t) {
            int r = ar + t * 64;
            size_t src = (size_t)(rowBase + r) * 512 + k0 + ac * 8;
            uint32_t dst = bb + r * 96 + ac * 16;
            CP16(dst,         Ah + src);
            CP16(dst + 12288, Al + src);
        }
        {
            size_t src = (size_t)(colBase + ar) * 512 + k0 + ac * 8;
            uint32_t dst = bb + 24576 + ar * 96 + ac * 16;
            CP16(dst,        Bh + src);
            CP16(dst + 6144, Bl + src);
        }
        CP_COMMIT();
    };

    float acc[2][4][4];
    #pragma unroll
    for (int mt = 0; mt < 2; ++mt)
        #pragma unroll
        for (int nt = 0; nt < 4; ++nt)
            #pragma unroll
            for (int r = 0; r < 4; ++r) acc[mt][nt][r] = 0.f;

    issue(sb, 0);

    for (int c = 0; c < 16; ++c) {
        const int cur = c & 1;
        const char* bufc = gsm + cur * 36864;
        if (c < 15) issue(sb + (cur ^ 1) * 36864, (c + 1) * 32);
        if (c < 15) asm volatile("cp.async.wait_group 1;" ::: "memory");
        else        asm volatile("cp.async.wait_group 0;" ::: "memory");
        __syncthreads();

        #pragma unroll
        for (int sub = 0; sub < 2; ++sub) {
            const int kbyte = sub * 32 + tig * 8;
            uint32_t ah[2][4], al[2][4];
            #pragma unroll
            for (int mt = 0; mt < 2; ++mt) {
                int r0 = wm + mt * 16 + grp;
                uint2 h0 = *(const uint2*)(bufc + r0 * 96 + kbyte);
                uint2 h1 = *(const uint2*)(bufc + (r0 + 8) * 96 + kbyte);
                uint2 l0 = *(const uint2*)(bufc + 12288 + r0 * 96 + kbyte);
                uint2 l1 = *(const uint2*)(bufc + 12288 + (r0 + 8) * 96 + kbyte);
                ah[mt][0] = h0.x; ah[mt][1] = h1.x; ah[mt][2] = h0.y; ah[mt][3] = h1.y;
                al[mt][0] = l0.x; al[mt][1] = l1.x; al[mt][2] = l0.y; al[mt][3] = l1.y;
            }
            #pragma unroll
            for (int nt = 0; nt < 4; ++nt) {
                int n = wn + nt * 8 + grp;
                uint2 bh2 = *(const uint2*)(bufc + 24576 + n * 96 + kbyte);
                uint2 bl2 = *(const uint2*)(bufc + 30720 + n * 96 + kbyte);
                #pragma unroll
                for (int mt = 0; mt < 2; ++mt) {
                    MMA_BF16(acc[mt][nt], ah[mt][0], ah[mt][1], ah[mt][2], ah[mt][3],
                             bh2.x, bh2.y);
                    MMA_BF16(acc[mt][nt], ah[mt][0], ah[mt][1], ah[mt][2], ah[mt][3],
                             bl2.x, bl2.y);
                    MMA_BF16(acc[mt][nt], al[mt][0], al[mt][1], al[mt][2], al[mt][3],
                             bh2.x, bh2.y);
                }
            }
        }
        __syncthreads();
    }

    if (z < 2) {
        // ---- Q/K epilogue: bf16 hi/lo, k-permuted columns ----
        __nv_bfloat16* Oh = (z == 0) ? qh : kh;
        __nv_bfloat16* Ol = (z == 0) ? ql : kl;
        const float scale = (z == 0) ? SCALE : 1.0f;
        #pragma unroll
        for (int nt = 0; nt < 4; ++nt) {
            int col = colBase + wn + nt * 8 + tig * 2;
            float b0 = __ldg(&bias[col]);
            float b1 = __ldg(&bias[col + 1]);
            int colp = (col & ~15) + perm16(col & 15);
            #pragma unroll
            for (int mt = 0; mt < 2; ++mt) {
                int row = rowBase + wm + mt * 16 + grp;
                float v00 = (acc[mt][nt][0] + b0) * scale;
                float v01 = (acc[mt][nt][1] + b1) * scale;
                float v10 = (acc[mt][nt][2] + b0) * scale;
                float v11 = (acc[mt][nt][3] + b1) * scale;
                __nv_bfloat162 h0 = __floats2bfloat162_rn(v00, v01);
                __nv_bfloat162 h1 = __floats2bfloat162_rn(v10, v11);
                __nv_bfloat162 l0 = __floats2bfloat162_rn(v00 - __bfloat162float(h0.x),
                                                          v01 - __bfloat162float(h0.y));
                __nv_bfloat162 l1 = __floats2bfloat162_rn(v10 - __bfloat162float(h1.x),
                                                          v11 - __bfloat162float(h1.y));
                *(uint32_t*)&Oh[(size_t)row       * 512 + colp] = b2u(h0);
                *(uint32_t*)&Oh[(size_t)(row + 8) * 512 + colp] = b2u(h1);
                *(uint32_t*)&Ol[(size_t)row       * 512 + colp] = b2u(l0);
                *(uint32_t*)&Ol[(size_t)(row + 8) * 512 + colp] = b2u(l1);
            }
        }
    } else {
        // ---- V epilogue: smem transpose -> [b][h][d][perm(c)] fp16 hi/lo ----
        constexpr int ST = 132;
        __half* tsh = (__half*)gsm;
        __half* tsl = tsh + 64 * ST;
        __syncthreads();
        #pragma unroll
        for (int nt = 0; nt < 4; ++nt) {
            int dl = wn + nt * 8 + tig * 2;
            float b0 = __ldg(&bias[colBase + dl]);
            float b1 = __ldg(&bias[colBase + dl + 1]);
            #pragma unroll
            for (int mt = 0; mt < 2; ++mt) {
                int rl = wm + mt * 16 + grp;
                float v00 = acc[mt][nt][0] + b0, v01 = acc[mt][nt][1] + b1;
                float v10 = acc[mt][nt][2] + b0, v11 = acc[mt][nt][3] + b1;
                __half h00 = __float2half_rn(v00);
                __half h01 = __float2half_rn(v01);
                __half h10 = __float2half_rn(v10);
                __half h11 = __float2half_rn(v11);
                tsh[(dl)     * ST + rl]     = h00;
                tsh[(dl + 1) * ST + rl]     = h01;
                tsh[(dl)     * ST + rl + 8] = h10;
                tsh[(dl + 1) * ST + rl + 8] = h11;
                tsl[(dl)     * ST + rl]     = __float2half_rn(v00 - __half2float(h00));
                tsl[(dl + 1) * ST + rl]     = __float2half_rn(v01 - __half2float(h01));
                tsl[(dl)     * ST + rl + 8] = __float2half_rn(v10 - __half2float(h10));
                tsl[(dl + 1) * ST + rl + 8] = __float2half_rn(v11 - __half2float(h11));
            }
        }
        __syncthreads();
        const int bb = rowBase >> 12;
        const int c0 = rowBase & 4095;
        const int hh = blockIdx.x;
        #pragma unroll
        for (int t = 0; t < 16; ++t) {
            int u  = tid + t * 256;
            int d  = u >> 6;
            int cl = (u & 63) * 2;
            uint32_t val_h = *(uint32_t*)&tsh[d * ST + cl];
            uint32_t val_l = *(uint32_t*)&tsl[d * ST + cl];
            int cp = (cl & ~15) + perm16(cl & 15);
            size_t o = ((size_t)(bb * H_ + hh) * 64 + d) * NC + c0 + cp;
            *(uint32_t*)&vth[o] = val_h;
            *(uint32_t*)&vtl[o] = val_l;
        }
    }
}

// ---------------------------------------------------------------------------
// O-projection GEMM (fp32 out).
// ---------------------------------------------------------------------------
__global__ __launch_bounds__(256, 2)
void gemm_o(const __nv_bfloat16* __restrict__ Ah, const __nv_bfloat16* __restrict__ Al,
            const __nv_bfloat16* __restrict__ Bh, const __nv_bfloat16* __restrict__ Bl,
            const float* __restrict__ bias, float* __restrict__ Yf) {
    extern __shared__ char gsm[];
    const uint32_t sb = smem_u32(gsm);

    const int tid  = threadIdx.x;
    const int lane = tid & 31;
    const int wid  = tid >> 5;
    const int grp  = lane >> 2;
    const int tig  = lane & 3;
    const int wm   = (wid >> 1) * 32;
    const int wn   = (wid & 1) * 32;
    const int rowBase = blockIdx.y * 128;
    const int colBase = blockIdx.x * 64;

    const int ar = tid >> 2;
    const int ac = tid & 3;

    auto issue = [&](uint32_t bb, int k0) {
        #pragma unroll
        for (int t = 0; t < 2; ++t) {
            int r = ar + t * 64;
            size_t src = (size_t)(rowBase + r) * 512 + k0 + ac * 8;
            uint32_t dst = bb + r * 96 + ac * 16;
            CP16(dst,         Ah + src);
            CP16(dst + 12288, Al + src);
        }
        {
            size_t src = (size_t)(colBase + ar) * 512 + k0 + ac * 8;
            uint32_t dst = bb + 24576 + ar * 96 + ac * 16;
            CP16(dst,        Bh + src);
            CP16(dst + 6144, Bl + src);
        }
        CP_COMMIT();
    };

    float acc[2][4][4];
    #pragma unroll
    for (int mt = 0; mt < 2; ++mt)
        #pragma unroll
        for (int nt = 0; nt < 4; ++nt)
            #pragma unroll
            for (int r = 0; r < 4; ++r) acc[mt][nt][r] = 0.f;

    issue(sb, 0);

    for (int c = 0; c < 16; ++c) {
        const int cur = c & 1;
        const char* bufc = gsm + cur * 36864;
        if (c < 15) issue(sb + (cur ^ 1) * 36864, (c + 1) * 32);
        if (c < 15) asm volatile("cp.async.wait_group 1;" ::: "memory");
        else        asm volatile("cp.async.wait_group 0;" ::: "memory");
        __syncthreads();

        #pragma unroll
        for (int sub = 0; sub < 2; ++sub) {
            const int kbyte = sub * 32 + tig * 8;
            uint32_t ah[2][4], al[2][4];
            #pragma unroll
            for (int mt = 0; mt < 2; ++mt) {
                int r0 = wm + mt * 16 + grp;
                uint2 h0 = *(const uint2*)(bufc + r0 * 96 + kbyte);
                uint2 h1 = *(const uint2*)(bufc + (r0 + 8) * 96 + kbyte);
                uint2 l0 = *(const uint2*)(bufc + 12288 + r0 * 96 + kbyte);
                uint2 l1 = *(const uint2*)(bufc + 12288 + (r0 + 8) * 96 + kbyte);
                ah[mt][0] = h0.x; ah[mt][1] = h1.x; ah[mt][2] = h0.y; ah[mt][3] = h1.y;
                al[mt][0] = l0.x; al[mt][1] = l1.x; al[mt][2] = l0.y; al[mt][3] = l1.y;
            }
            #pragma unroll
            for (int nt = 0; nt < 4; ++nt) {
                int n = wn + nt * 8 + grp;
                uint2 bh2 = *(const uint2*)(bufc + 24576 + n * 96 + kbyte);
                uint2 bl2 = *(const uint2*)(bufc + 30720 + n * 96 + kbyte);
                #pragma unroll
                for (int mt = 0; mt < 2; ++mt) {
                    MMA_BF16(acc[mt][nt], ah[mt][0], ah[mt][1], ah[mt][2], ah[mt][3],
                             bh2.x, bh2.y);
                    MMA_BF16(acc[mt][nt], ah[mt][0], ah[mt][1], ah[mt][2], ah[mt][3],
                             bl2.x, bl2.y);
                    MMA_BF16(acc[mt][nt], al[mt][0], al[mt][1], al[mt][2], al[mt][3],
                             bh2.x, bh2.y);
                }
            }
        }
        __syncthreads();
    }

    #pragma unroll
    for (int nt = 0; nt < 4; ++nt) {
        int col = colBase + wn + nt * 8 + tig * 2;
        float b0 = __ldg(&bias[col]);
        float b1 = __ldg(&bias[col + 1]);
        #pragma unroll
        for (int mt = 0; mt < 2; ++mt) {
            int row = rowBase + wm + mt * 16 + grp;
            *(float2*)&Yf[(size_t)row       * 512 + col] =
                make_float2(acc[mt][nt][0] + b0, acc[mt][nt][1] + b1);
            *(float2*)&Yf[(size_t)(row + 8) * 512 + col] =
                make_float2(acc[mt][nt][2] + b0, acc[mt][nt][3] + b1);
        }
    }
}

// ---------------------------------------------------------------------------
// Tensor-core flash attention v6 (R11 structure + fp16 P / fp16 V hi-lo AV).
// QK: bf16 3-pass (unchanged).  AV: 2-pass f16 (P*Vh + P*Vl).
// Smem: buf[2] of 40960  {Kh 0 | Kl 10240 | Vh 20480 | Vl 30720}.  81920 total.
// ---------------------------------------------------------------------------
constexpr int ATTN_SMEM_B = 81920;

__global__ __launch_bounds__(256, 2)
void attn_tc(const __nv_bfloat16* __restrict__ qh, const __nv_bfloat16* __restrict__ ql,
             const __nv_bfloat16* __restrict__ kh, const __nv_bfloat16* __restrict__ kl,
             const __half* __restrict__ vth, const __half* __restrict__ vtl,
             const __half* __restrict__ heat,
             __nv_bfloat16* __restrict__ yh, __nv_bfloat16* __restrict__ yl) {
    extern __shared__ char smem[];
    const uint32_t sb = smem_u32(smem);

    const int b   = blockIdx.z;
    const int h   = blockIdx.y;
    const int q0  = blockIdx.x * 128;
    const int tid = threadIdx.x;
    const int w    = tid >> 5;
    const int lane = tid & 31;
    const int grp  = lane >> 2;
    const int tig  = lane & 3;

    const int sr  = tid >> 3;
    const int sc8 = tid & 7;

    auto issue_tile = [&](uint32_t bb, int c0) {
        #pragma unroll
        for (int j = 0; j < 2; ++j) {
            int r = sr + j * 32;
            size_t ksrc = (size_t)(b * NC + c0 + r) * 512 + h * 64 + sc8 * 8;
            size_t vsrc = ((size_t)(b * H_ + h) * 64 + r) * NC + c0 + sc8 * 8;
            uint32_t d0 = bb + r * 160 + sc8 * 16;
            CP16(d0,         kh  + ksrc);
            CP16(d0 + 10240, kl  + ksrc);
            CP16(d0 + 20480, vth + vsrc);
            CP16(d0 + 30720, vtl + vsrc);
        }
        CP_COMMIT();
    };

    const int qrow0 = b * NQ + q0 + w * 16 + grp;
    uint32_t qfh[4][4], qfl[4][4];
    #pragma unroll
    for (int ks = 0; ks < 4; ++ks) {
        size_t e0 = (size_t)qrow0 * 512 + h * 64 + ks * 16 + tig * 4;
        size_t e1 = e0 + (size_t)8 * 512;
        uint2 h0 = *(const uint2*)(qh + e0);
        uint2 h1 = *(const uint2*)(qh + e1);
        uint2 l0v = *(const uint2*)(ql + e0);
        uint2 l1v = *(const uint2*)(ql + e1);
        qfh[ks][0] = h0.x; qfh[ks][1] = h1.x; qfh[ks][2] = h0.y; qfh[ks][3] = h1.y;
        qfl[ks][0] = l0v.x; qfl[ks][1] = l1v.x; qfl[ks][2] = l0v.y; qfl[ks][3] = l1v.y;
    }

    float acc[8][4];
    #pragma unroll
    for (int m = 0; m < 8; ++m)
        #pragma unroll
        for (int r = 0; r < 4; ++r) acc[m][r] = 0.f;
    float lq0 = 0.f, lq8 = 0.f;

    const __half* hb0 = heat + (size_t)qrow0 * NC;
    const __half* hb1 = hb0 + (size_t)8 * NC;

    auto qk_chunk = [&](const char* bufc, int kc, float* s0, float* s1) {
        #pragma unroll
        for (int ks = 0; ks < 4; ++ks) {
            int r0 = (kc * 16 + grp) * 160 + ks * 32 + tig * 8;
            int r1 = r0 + 8 * 160;
            uint2 k0h = *(const uint2*)(bufc + r0);
            uint2 k0l = *(const uint2*)(bufc + 10240 + r0);
            uint2 k1h = *(const uint2*)(bufc + r1);
            uint2 k1l = *(const uint2*)(bufc + 10240 + r1);
            MMA_BF16(s0, qfh[ks][0], qfh[ks][1], qfh[ks][2], qfh[ks][3], k0h.x, k0h.y);
            MMA_BF16(s0, qfh[ks][0], qfh[ks][1], qfh[ks][2], qfh[ks][3], k0l.x, k0l.y);
            MMA_BF16(s0, qfl[ks][0], qfl[ks][1], qfl[ks][2], qfl[ks][3], k0h.x, k0h.y);
            MMA_BF16(s1, qfh[ks][0], qfh[ks][1], qfh[ks][2], qfh[ks][3], k1h.x, k1h.y);
            MMA_BF16(s1, qfh[ks][0], qfh[ks][1], qfh[ks][2], qfh[ks][3], k1l.x, k1l.y);
            MMA_BF16(s1, qfl[ks][0], qfl[ks][1], qfl[ks][2], qfl[ks][3], k1h.x, k1h.y);
        }
    };

    issue_tile(sb, 0);

    for (int it = 0; it < 64; ++it) {
        const int cur = it & 1;
        const char* bufc = smem + cur * 40960;
        if (it < 63) issue_tile(sb + (cur ^ 1) * 40960, (it + 1) * 64);
        if (it < 63) asm volatile("cp.async.wait_group 1;" ::: "memory");
        else         asm volatile("cp.async.wait_group 0;" ::: "memory");
        __syncthreads();

        const int c0 = it * 64;
        uint32_t HA0 = *(const uint32_t*)(hb0 + c0 + tig * 2);
        uint32_t HA1 = *(const uint32_t*)(hb1 + c0 + tig * 2);
        uint32_t HB0 = *(const uint32_t*)(hb0 + c0 + 8 + tig * 2);
        uint32_t HB1 = *(const uint32_t*)(hb1 + c0 + 8 + tig * 2);

        float s0[4] = {0.f, 0.f, 0.f, 0.f};
        float s1[4] = {0.f, 0.f, 0.f, 0.f};
        qk_chunk(bufc, 0, s0, s1);

        #pragma unroll
        for (int kc = 0; kc < 4; ++kc) {
            float2 ha0 = __half22float2(*(const __half2*)&HA0);
            float2 ha1 = __half22float2(*(const __half2*)&HA1);
            float2 hc0 = __half22float2(*(const __half2*)&HB0);
            float2 hc1 = __half22float2(*(const __half2*)&HB1);
            if (kc < 3) {
                int nb = c0 + (kc + 1) * 16 + tig * 2;
                HA0 = *(const uint32_t*)(hb0 + nb);
                HA1 = *(const uint32_t*)(hb1 + nb);
                HB0 = *(const uint32_t*)(hb0 + nb + 8);
                HB1 = *(const uint32_t*)(hb1 + nb + 8);
            }

            // ---- exp + pack P as fp16 (11-bit mantissa: P-lo pass unneeded) ----
            float e00 = __expf(s0[0] + ha0.x);
            float e01 = __expf(s0[1] + ha0.y);
            float e10 = __expf(s0[2] + ha1.x);
            float e11 = __expf(s0[3] + ha1.y);
            lq0 += e00 + e01;
            lq8 += e10 + e11;
            float f00 = __expf(s1[0] + hc0.x);
            float f01 = __expf(s1[1] + hc0.y);
            float f10 = __expf(s1[2] + hc1.x);
            float f11 = __expf(s1[3] + hc1.y);
            lq0 += f00 + f01;
            lq8 += f10 + f11;
            uint32_t a0 = h2u(__floats2half2_rn(e00, e01));
            uint32_t a1 = h2u(__floats2half2_rn(e10, e11));
            uint32_t a2 = h2u(__floats2half2_rn(f00, f01));
            uint32_t a3 = h2u(__floats2half2_rn(f10, f11));

            float t0[4] = {0.f, 0.f, 0.f, 0.f};
            float t1[4] = {0.f, 0.f, 0.f, 0.f};
            if (kc < 3) qk_chunk(bufc, kc + 1, t0, t1);

            // ---- AV (2-pass f16: P*Vh + P*Vl) ----
            #pragma unroll
            for (int m = 0; m < 8; ++m) {
                int boff = 20480 + (m * 8 + grp) * 160 + kc * 32 + tig * 8;
                uint2 vh2 = *(const uint2*)(bufc + boff);
                uint2 vl2 = *(const uint2*)(bufc + boff + 10240);
                MMA_F16(acc[m], a0, a1, a2, a3, vh2.x, vh2.y);
                MMA_F16(acc[m], a0, a1, a2, a3, vl2.x, vl2.y);
            }

            #pragma unroll
            for (int r = 0; r < 4; ++r) { s0[r] = t0[r]; s1[r] = t1[r]; }
        }
        __syncthreads();
    }

    lq0 += __shfl_xor_sync(0xffffffffu, lq0, 1);
    lq0 += __shfl_xor_sync(0xffffffffu, lq0, 2);
    lq8 += __shfl_xor_sync(0xffffffffu, lq8, 1);
    lq8 += __shfl_xor_sync(0xffffffffu, lq8, 2);
    float i0 = 1.0f / lq0;
    float i1 = 1.0f / lq8;

    size_t yr0 = (size_t)qrow0 * 512 + h * 64;
    size_t yr1 = yr0 + (size_t)8 * 512;
    #pragma unroll
    for (int nt = 0; nt < 8; ++nt) {
        int ccp = (nt >> 1) * 16 + (nt & 1) * 2 + tig * 4;   // d-permuted
        float v00 = acc[nt][0] * i0, v01 = acc[nt][1] * i0;
        float v10 = acc[nt][2] * i1, v11 = acc[nt][3] * i1;
        __nv_bfloat162 h0 = __floats2bfloat162_rn(v00, v01);
        __nv_bfloat162 h1 = __floats2bfloat162_rn(v10, v11);
        __nv_bfloat162 l0v = __floats2bfloat162_rn(v00 - __bfloat162float(h0.x),
                                                   v01 - __bfloat162float(h0.y));
        __nv_bfloat162 l1v = __floats2bfloat162_rn(v10 - __bfloat162float(h1.x),
                                                   v11 - __bfloat162float(h1.y));
        *(uint32_t*)&yh[yr0 + ccp] = b2u(h0);
        *(uint32_t*)&yh[yr1 + ccp] = b2u(h1);
        *(uint32_t*)&yl[yr0 + ccp] = b2u(l0v);
        *(uint32_t*)&yl[yr1 + ccp] = b2u(l1v);
    }
}

// ---------------------------------------------------------------------------
// Launch (attn_tc at index 3 for ncu).
// ---------------------------------------------------------------------------
extern "C" void kernel_launch(void* const* d_in, const int* in_sizes, int n_in,
                              void* d_out, int out_size) {
    (void)in_sizes; (void)n_in; (void)out_size;
    const float* x_ctx     = (const float*)d_in[0];
    const float* x_query   = (const float*)d_in[1];
    const float* pos_ctx   = (const float*)d_in[2];
    const float* pos_query = (const float*)d_in[3];
    const float* Wq = (const float*)d_in[4];
    const float* bq = (const float*)d_in[5];
    const float* Wk = (const float*)d_in[6];
    const float* bk = (const float*)d_in[7];
    const float* Wv = (const float*)d_in[8];
    const float* bv = (const float*)d_in[9];
    const float* Wo = (const float*)d_in[10];
    const float* bo = (const float*)d_in[11];
    float* out = (float*)d_out;

    __half *gh, *gvth, *gvtl;
    __nv_bfloat16 *gxqh, *gxql, *gxch, *gxcl, *gwh, *gwl;
    __nv_bfloat16 *gqh, *gql, *gkh, *gkl, *gyh, *gyl;
    cudaGetSymbolAddress((void**)&gh,   g_heat);
    cudaGetSymbolAddress((void**)&gxqh, g_xqh);
    cudaGetSymbolAddress((void**)&gxql, g_xql);
    cudaGetSymbolAddress((void**)&gxch, g_xch);
    cudaGetSymbolAddress((void**)&gxcl, g_xcl);
    cudaGetSymbolAddress((void**)&gwh,  g_wh);
    cudaGetSymbolAddress((void**)&gwl,  g_wl);
    cudaGetSymbolAddress((void**)&gqh,  g_qh);
    cudaGetSymbolAddress((void**)&gql,  g_ql);
    cudaGetSymbolAddress((void**)&gkh,  g_kh);
    cudaGetSymbolAddress((void**)&gkl,  g_kl);
    cudaGetSymbolAddress((void**)&gvth, g_vth);
    cudaGetSymbolAddress((void**)&gvtl, g_vtl);
    cudaGetSymbolAddress((void**)&gyh,  g_yh);
    cudaGetSymbolAddress((void**)&gyl,  g_yl);

    cudaFuncSetAttribute(attn_tc,
                         cudaFuncAttributeMaxDynamicSharedMemorySize, ATTN_SMEM_B);
    cudaFuncSetAttribute(proj_qkv,
                         cudaFuncAttributeMaxDynamicSharedMemorySize, GEMM_SMEM_B);
    cudaFuncSetAttribute(gemm_o,
                         cudaFuncAttributeMaxDynamicSharedMemorySize, GEMM_SMEM_B);

    // launch 0
    split_all<<<(B_ * NQ * CE + B_ * NC * CE) / 1024 + 4 * (CE * CE) / 1024, 256>>>(
        x_query, x_ctx, Wq, Wk, Wv, Wo, gxqh, gxql, gxch, gxcl, gwh, gwl);
    // launch 1
    heat_precompute<<<dim3(NQ, B_), 256>>>(pos_ctx, pos_query, gh);
    // launch 2
    proj_qkv<<<dim3(8, 64, 3), 256, GEMM_SMEM_B>>>(
        gxqh, gxql, gxch, gxcl, gwh, gwl, bq, bk, bv,
        gqh, gql, gkh, gkl, gvth, gvtl);
    // launch 3: attention (profiled)
    attn_tc<<<dim3(NQ / 128, H_, B_), 256, ATTN_SMEM_B>>>(
        gqh, gql, gkh, gkl, gvth, gvtl, gh, gyh, gyl);
    // launch 4
    gemm_o<<<dim3(8, (B_ * NQ) / 128), 256, GEMM_SMEM_B>>>(
        gyh, gyl, gwh + 3 * CE * CE, gwl + 3 * CE * CE, bo, out);
}

// round 17
// speedup vs baseline: 1.4445x; 1.1821x over previous
#include <cuda_runtime.h>
#include <cuda_bf16.h>
#include <cuda_fp16.h>
#include <cstdint>
#include <math.h>

// ---------------------------------------------------------------------------
// Problem constants
// ---------------------------------------------------------------------------
constexpr int B_  = 2;
constexpr int NQ  = 2048;
constexpr int NC  = 4096;
constexpr int CE  = 512;
constexpr int H_  = 8;
constexpr float SCALE  = 0.125f;
constexpr float FOURNU = 0.4f;
constexpr float EPS_   = 1e-6f;

// Pair-interleave permutation within a 16-element k-chunk (validated R7+).
__host__ __device__ constexpr int perm16(int e) {
    int lp = e >> 1, o = e & 1;
    int slot = (lp < 4) ? (lp * 2) : ((lp - 4) * 2 + 1);
    return slot * 2 + o;
}

// ---------------------------------------------------------------------------
// Scratch.  Q: fp16 hi/lo (repr ~2^-23).  K, V: single fp16 (quant 2^-11;
// output contribution ~1e-4 / ~1.7e-4 per calibrated transfer model).
// ---------------------------------------------------------------------------
__device__ __half g_heat[(size_t)B_ * NQ * NC];           // 33.5 MB (fp16)
__device__ __nv_bfloat16 g_xqh[B_ * NQ * CE];
__device__ __nv_bfloat16 g_xql[B_ * NQ * CE];
__device__ __nv_bfloat16 g_xch[B_ * NC * CE];
__device__ __nv_bfloat16 g_xcl[B_ * NC * CE];
__device__ __nv_bfloat16 g_wh[4 * CE * CE];
__device__ __nv_bfloat16 g_wl[4 * CE * CE];
__device__ __half g_qh[B_ * NQ * CE];                     // scaled, d-permuted, fp16 hi
__device__ __half g_ql[B_ * NQ * CE];                     // fp16 lo
__device__ __half g_kf[B_ * NC * CE];                     // d-permuted, fp16 single
__device__ __half g_vtf[B_ * NC * CE];                    // [b][h][d][c], c-permuted, fp16
__device__ __nv_bfloat16 g_yh[B_ * NQ * CE];              // attn out, d-permuted
__device__ __nv_bfloat16 g_yl[B_ * NQ * CE];

// ---------------------------------------------------------------------------
// helpers
// ---------------------------------------------------------------------------
#define MMA_BF16(d, a0, a1, a2, a3, b0, b1) \
    asm volatile("mma.sync.aligned.m16n8k16.row.col.f32.bf16.bf16.f32 " \
        "{%0,%1,%2,%3}, {%4,%5,%6,%7}, {%8,%9}, {%0,%1,%2,%3};" \
        : "+f"((d)[0]), "+f"((d)[1]), "+f"((d)[2]), "+f"((d)[3]) \
        : "r"(a0), "r"(a1), "r"(a2), "r"(a3), "r"(b0), "r"(b1))

#define MMA_F16(d, a0, a1, a2, a3, b0, b1) \
    asm volatile("mma.sync.aligned.m16n8k16.row.col.f32.f16.f16.f32 " \
        "{%0,%1,%2,%3}, {%4,%5,%6,%7}, {%8,%9}, {%0,%1,%2,%3};" \
        : "+f"((d)[0]), "+f"((d)[1]), "+f"((d)[2]), "+f"((d)[3]) \
        : "r"(a0), "r"(a1), "r"(a2), "r"(a3), "r"(b0), "r"(b1))

#define CP16(dst, src) \
    asm volatile("cp.async.cg.shared.global [%0], [%1], 16;" \
                 :: "r"(dst), "l"(src))
#define CP_COMMIT() asm volatile("cp.async.commit_group;")

__device__ __forceinline__ uint32_t b2u(__nv_bfloat162 x) {
    return *reinterpret_cast<uint32_t*>(&x);
}
__device__ __forceinline__ uint32_t h2u(__half2 x) {
    return *reinterpret_cast<uint32_t*>(&x);
}
__device__ __forceinline__ uint32_t smem_u32(const void* p) {
    uint32_t a;
    asm("{ .reg .u64 t; cvta.to.shared.u64 t, %1; cvt.u32.u64 %0, t; }"
        : "=r"(a) : "l"(p));
    return a;
}

// ---------------------------------------------------------------------------
// Heat-kernel bias precompute -> fp16
// ---------------------------------------------------------------------------
__global__ __launch_bounds__(256)
void heat_precompute(const float* __restrict__ pos_c, const float* __restrict__ pos_q,
                     __half* __restrict__ heat) {
    const int b  = blockIdx.y;
    const int qi = blockIdx.x;
    const float* pq = pos_q + (size_t)(b * NQ + qi) * 3;
    const float qx = pq[0], qy = pq[1], qt = pq[2];
    __half2* hrow = (__half2*)(heat + ((size_t)b * NQ + qi) * NC);
    for (int c2 = threadIdx.x; c2 < NC / 2; c2 += 256) {
        const float* pc = pos_c + (size_t)(b * NC + c2 * 2) * 3;
        float dx0 = qx - pc[0], dy0 = qy - pc[1], dt0 = qt - pc[2];
        float dx1 = qx - pc[3], dy1 = qy - pc[4], dt1 = qt - pc[5];
        float e0 = __expf(-__fdividef(dx0 * dx0 + dy0 * dy0,
                                      FOURNU * fabsf(dt0) + EPS_));
        float e1 = __expf(-__fdividef(dx1 * dx1 + dy1 * dy1,
                                      FOURNU * fabsf(dt1) + EPS_));
        hrow[c2] = __floats2half2_rn(e0, e1);
    }
}

// ---------------------------------------------------------------------------
// bf16 hi/lo split body (k-pair-interleaved output)
// ---------------------------------------------------------------------------
__device__ __forceinline__ void split_body(const float* __restrict__ in,
                                           __nv_bfloat16* __restrict__ oh,
                                           __nv_bfloat16* __restrict__ ol, int i) {
    float4 v = ((const float4*)in)[i];
    __nv_bfloat162 hA = __floats2bfloat162_rn(v.x, v.y);
    __nv_bfloat162 hB = __floats2bfloat162_rn(v.z, v.w);
    __nv_bfloat162 lA = __floats2bfloat162_rn(v.x - __bfloat162float(hA.x),
                                              v.y - __bfloat162float(hA.y));
    __nv_bfloat162 lB = __floats2bfloat162_rn(v.z - __bfloat162float(hB.x),
                                              v.w - __bfloat162float(hB.y));
    size_t e = (size_t)i * 4;
    size_t base = e & ~(size_t)15;
    int lp0 = (int)(e & 15) >> 1;
    int s0 = (lp0 < 4) ? lp0 * 2 : (lp0 - 4) * 2 + 1;
    int lp1 = lp0 + 1;
    int s1 = (lp1 < 4) ? lp1 * 2 : (lp1 - 4) * 2 + 1;
    *(uint32_t*)&oh[base + s0 * 2] = b2u(hA);
    *(uint32_t*)&oh[base + s1 * 2] = b2u(hB);
    *(uint32_t*)&ol[base + s0 * 2] = b2u(lA);
    *(uint32_t*)&ol[base + s1 * 2] = b2u(lB);
}

__global__ __launch_bounds__(256)
void split_all(const float* __restrict__ xq, const float* __restrict__ xc,
               const float* __restrict__ w0, const float* __restrict__ w1,
               const float* __restrict__ w2, const float* __restrict__ w3,
               __nv_bfloat16* __restrict__ oqh, __nv_bfloat16* __restrict__ oql,
               __nv_bfloat16* __restrict__ och, __nv_bfloat16* __restrict__ ocl,
               __nv_bfloat16* __restrict__ owh, __nv_bfloat16* __restrict__ owl) {
    constexpr int NBQ = (B_ * NQ * CE) / 1024;
    constexpr int NBC = (B_ * NC * CE) / 1024;
    constexpr int NBW = (CE * CE) / 1024;
    int bid = blockIdx.x;
    if (bid < NBQ) {
        split_body(xq, oqh, oql, bid * 256 + threadIdx.x);
    } else if (bid < NBQ + NBC) {
        split_body(xc, och, ocl, (bid - NBQ) * 256 + threadIdx.x);
    } else {
        int wb = bid - NBQ - NBC;
        int j  = wb / NBW;
        const float* in = (j == 0) ? w0 : (j == 1) ? w1 : (j == 2) ? w2 : w3;
        size_t off = (size_t)j * CE * CE;
        split_body(in, owh + off, owl + off, (wb - j * NBW) * 256 + threadIdx.x);
    }
}

// ---------------------------------------------------------------------------
// Batched Q/K/V projection GEMM.  z=0: Q (fp16 hi/lo, d-permuted, scaled).
// z=1: K (fp16 single, d-permuted).  z=2: V -> per-head transpose, fp16 single.
// ---------------------------------------------------------------------------
constexpr int GEMM_SMEM_B = 73728;

__global__ __launch_bounds__(256, 2)
void proj_qkv(const __nv_bfloat16* __restrict__ xqh, const __nv_bfloat16* __restrict__ xql,
              const __nv_bfloat16* __restrict__ xch, const __nv_bfloat16* __restrict__ xcl,
              const __nv_bfloat16* __restrict__ wh,  const __nv_bfloat16* __restrict__ wl,
              const float* __restrict__ bq, const float* __restrict__ bk,
              const float* __restrict__ bv,
              __half* __restrict__ qh, __half* __restrict__ ql,
              __half* __restrict__ kf, __half* __restrict__ vtf) {
    const int z = blockIdx.z;
    const int nrows = (z == 0) ? 32 : 64;
    if (blockIdx.y >= nrows) return;

    const __nv_bfloat16* Ah = (z == 0) ? xqh : xch;
    const __nv_bfloat16* Al = (z == 0) ? xql : xcl;
    const __nv_bfloat16* Bh = wh + (size_t)z * CE * CE;
    const __nv_bfloat16* Bl = wl + (size_t)z * CE * CE;
    const float* bias = (z == 0) ? bq : (z == 1) ? bk : bv;

    extern __shared__ char gsm[];
    const uint32_t sb = smem_u32(gsm);

    const int tid  = threadIdx.x;
    const int lane = tid & 31;
    const int wid  = tid >> 5;
    const int grp  = lane >> 2;
    const int tig  = lane & 3;
    const int wm   = (wid >> 1) * 32;
    const int wn   = (wid & 1) * 32;
    const int rowBase = blockIdx.y * 128;
    const int colBase = blockIdx.x * 64;

    const int ar = tid >> 2;
    const int ac = tid & 3;

    auto issue = [&](uint32_t bb, int k0) {
        #pragma unroll
        for (int t = 0; t < 2; ++t) {
            int r = ar + t * 64;
            size_t src = (size_t)(rowBase + r) * 512 + k0 + ac * 8;
            uint32_t dst = bb + r * 96 + ac * 16;
            CP16(dst,         Ah + src);
            CP16(dst + 12288, Al + src);
        }
        {
            size_t src = (size_t)(colBase + ar) * 512 + k0 + ac * 8;
            uint32_t dst = bb + 24576 + ar * 96 + ac * 16;
            CP16(dst,        Bh + src);
            CP16(dst + 6144, Bl + src);
        }
        CP_COMMIT();
    };

    float acc[2][4][4];
    #pragma unroll
    for (int mt = 0; mt < 2; ++mt)
        #pragma unroll
        for (int nt = 0; nt < 4; ++nt)
            #pragma unroll
            for (int r = 0; r < 4; ++r) acc[mt][nt][r] = 0.f;

    issue(sb, 0);

    for (int c = 0; c < 16; ++c) {
        const int cur = c & 1;
        const char* bufc = gsm + cur * 36864;
        if (c < 15) issue(sb + (cur ^ 1) * 36864, (c + 1) * 32);
        if (c < 15) asm volatile("cp.async.wait_group 1;" ::: "memory");
        else        asm volatile("cp.async.wait_group 0;" ::: "memory");
        __syncthreads();

        #pragma unroll
        for (int sub = 0; sub < 2; ++sub) {
            const int kbyte = sub * 32 + tig * 8;
            uint32_t ah[2][4], al[2][4];
            #pragma unroll
            for (int mt = 0; mt < 2; ++mt) {
                int r0 = wm + mt * 16 + grp;
                uint2 h0 = *(const uint2*)(bufc + r0 * 96 + kbyte);
                uint2 h1 = *(const uint2*)(bufc + (r0 + 8) * 96 + kbyte);
                uint2 l0 = *(const uint2*)(bufc + 12288 + r0 * 96 + kbyte);
                uint2 l1 = *(const uint2*)(bufc + 12288 + (r0 + 8) * 96 + kbyte);
                ah[mt][0] = h0.x; ah[mt][1] = h1.x; ah[mt][2] = h0.y; ah[mt][3] = h1.y;
                al[mt][0] = l0.x; al[mt][1] = l1.x; al[mt][2] = l0.y; al[mt][3] = l1.y;
            }
            #pragma unroll
            for (int nt = 0; nt < 4; ++nt) {
                int n = wn + nt * 8 + grp;
                uint2 bh2 = *(const uint2*)(bufc + 24576 + n * 96 + kbyte);
                uint2 bl2 = *(const uint2*)(bufc + 30720 + n * 96 + kbyte);
                #pragma unroll
                for (int mt = 0; mt < 2; ++mt) {
                    MMA_BF16(acc[mt][nt], ah[mt][0], ah[mt][1], ah[mt][2], ah[mt][3],
                             bh2.x, bh2.y);
                    MMA_BF16(acc[mt][nt], ah[mt][0], ah[mt][1], ah[mt][2], ah[mt][3],
                             bl2.x, bl2.y);
                    MMA_BF16(acc[mt][nt], al[mt][0], al[mt][1], al[mt][2], al[mt][3],
                             bh2.x, bh2.y);
                }
            }
        }
        __syncthreads();
    }

    if (z == 0) {
        // ---- Q epilogue: fp16 hi/lo, k-permuted, scaled ----
        #pragma unroll
        for (int nt = 0; nt < 4; ++nt) {
            int col = colBase + wn + nt * 8 + tig * 2;
            float b0 = __ldg(&bias[col]);
            float b1 = __ldg(&bias[col + 1]);
            int colp = (col & ~15) + perm16(col & 15);
            #pragma unroll
            for (int mt = 0; mt < 2; ++mt) {
                int row = rowBase + wm + mt * 16 + grp;
                float v00 = (acc[mt][nt][0] + b0) * SCALE;
                float v01 = (acc[mt][nt][1] + b1) * SCALE;
                float v10 = (acc[mt][nt][2] + b0) * SCALE;
                float v11 = (acc[mt][nt][3] + b1) * SCALE;
                __half2 h0 = __floats2half2_rn(v00, v01);
                __half2 h1 = __floats2half2_rn(v10, v11);
                __half2 l0 = __floats2half2_rn(v00 - __half2float(__low2half(h0)),
                                               v01 - __half2float(__high2half(h0)));
                __half2 l1 = __floats2half2_rn(v10 - __half2float(__low2half(h1)),
                                               v11 - __half2float(__high2half(h1)));
                *(uint32_t*)&qh[(size_t)row       * 512 + colp] = h2u(h0);
                *(uint32_t*)&qh[(size_t)(row + 8) * 512 + colp] = h2u(h1);
                *(uint32_t*)&ql[(size_t)row       * 512 + colp] = h2u(l0);
                *(uint32_t*)&ql[(size_t)(row + 8) * 512 + colp] = h2u(l1);
            }
        }
    } else if (z == 1) {
        // ---- K epilogue: fp16 single, k-permuted ----
        #pragma unroll
        for (int nt = 0; nt < 4; ++nt) {
            int col = colBase + wn + nt * 8 + tig * 2;
            float b0 = __ldg(&bias[col]);
            float b1 = __ldg(&bias[col + 1]);
            int colp = (col & ~15) + perm16(col & 15);
            #pragma unroll
            for (int mt = 0; mt < 2; ++mt) {
                int row = rowBase + wm + mt * 16 + grp;
                __half2 h0 = __floats2half2_rn(acc[mt][nt][0] + b0, acc[mt][nt][1] + b1);
                __half2 h1 = __floats2half2_rn(acc[mt][nt][2] + b0, acc[mt][nt][3] + b1);
                *(uint32_t*)&kf[(size_t)row       * 512 + colp] = h2u(h0);
                *(uint32_t*)&kf[(size_t)(row + 8) * 512 + colp] = h2u(h1);
            }
        }
    } else {
        // ---- V epilogue: smem transpose -> [b][h][d][perm(c)] fp16 single ----
        constexpr int ST = 132;
        __half* tsh = (__half*)gsm;
        __syncthreads();
        #pragma unroll
        for (int nt = 0; nt < 4; ++nt) {
            int dl = wn + nt * 8 + tig * 2;
            float b0 = __ldg(&bias[colBase + dl]);
            float b1 = __ldg(&bias[colBase + dl + 1]);
            #pragma unroll
            for (int mt = 0; mt < 2; ++mt) {
                int rl = wm + mt * 16 + grp;
                tsh[(dl)     * ST + rl]     = __float2half_rn(acc[mt][nt][0] + b0);
                tsh[(dl + 1) * ST + rl]     = __float2half_rn(acc[mt][nt][1] + b1);
                tsh[(dl)     * ST + rl + 8] = __float2half_rn(acc[mt][nt][2] + b0);
                tsh[(dl + 1) * ST + rl + 8] = __float2half_rn(acc[mt][nt][3] + b1);
            }
        }
        __syncthreads();
        const int bb = rowBase >> 12;
        const int c0 = rowBase & 4095;
        const int hh = blockIdx.x;
        #pragma unroll
        for (int t = 0; t < 16; ++t) {
            int u  = tid + t * 256;
            int d  = u >> 6;
            int cl = (u & 63) * 2;
            uint32_t val = *(uint32_t*)&tsh[d * ST + cl];
            int cp = (cl & ~15) + perm16(cl & 15);
            size_t o = ((size_t)(bb * H_ + hh) * 64 + d) * NC + c0 + cp;
            *(uint32_t*)&vtf[o] = val;
        }
    }
}

// ---------------------------------------------------------------------------
// O-projection GEMM (fp32 out).
// ---------------------------------------------------------------------------
__global__ __launch_bounds__(256, 2)
void gemm_o(const __nv_bfloat16* __restrict__ Ah, const __nv_bfloat16* __restrict__ Al,
            const __nv_bfloat16* __restrict__ Bh, const __nv_bfloat16* __restrict__ Bl,
            const float* __restrict__ bias, float* __restrict__ Yf) {
    extern __shared__ char gsm[];
    const uint32_t sb = smem_u32(gsm);

    const int tid  = threadIdx.x;
    const int lane = tid & 31;
    const int wid  = tid >> 5;
    const int grp  = lane >> 2;
    const int tig  = lane & 3;
    const int wm   = (wid >> 1) * 32;
    const int wn   = (wid & 1) * 32;
    const int rowBase = blockIdx.y * 128;
    const int colBase = blockIdx.x * 64;

    const int ar = tid >> 2;
    const int ac = tid & 3;

    auto issue = [&](uint32_t bb, int k0) {
        #pragma unroll
        for (int t = 0; t < 2; ++t) {
            int r = ar + t * 64;
            size_t src = (size_t)(rowBase + r) * 512 + k0 + ac * 8;
            uint32_t dst = bb + r * 96 + ac * 16;
            CP16(dst,         Ah + src);
            CP16(dst + 12288, Al + src);
        }
        {
            size_t src = (size_t)(colBase + ar) * 512 + k0 + ac * 8;
            uint32_t dst = bb + 24576 + ar * 96 + ac * 16;
            CP16(dst,        Bh + src);
            CP16(dst + 6144, Bl + src);
        }
        CP_COMMIT();
    };

    float acc[2][4][4];
    #pragma unroll
    for (int mt = 0; mt < 2; ++mt)
        #pragma unroll
        for (int nt = 0; nt < 4; ++nt)
            #pragma unroll
            for (int r = 0; r < 4; ++r) acc[mt][nt][r] = 0.f;

    issue(sb, 0);

    for (int c = 0; c < 16; ++c) {
        const int cur = c & 1;
        const char* bufc = gsm + cur * 36864;
        if (c < 15) issue(sb + (cur ^ 1) * 36864, (c + 1) * 32);
        if (c < 15) asm volatile("cp.async.wait_group 1;" ::: "memory");
        else        asm volatile("cp.async.wait_group 0;" ::: "memory");
        __syncthreads();

        #pragma unroll
        for (int sub = 0; sub < 2; ++sub) {
            const int kbyte = sub * 32 + tig * 8;
            uint32_t ah[2][4], al[2][4];
            #pragma unroll
            for (int mt = 0; mt < 2; ++mt) {
                int r0 = wm + mt * 16 + grp;
                uint2 h0 = *(const uint2*)(bufc + r0 * 96 + kbyte);
                uint2 h1 = *(const uint2*)(bufc + (r0 + 8) * 96 + kbyte);
                uint2 l0 = *(const uint2*)(bufc + 12288 + r0 * 96 + kbyte);
                uint2 l1 = *(const uint2*)(bufc + 12288 + (r0 + 8) * 96 + kbyte);
                ah[mt][0] = h0.x; ah[mt][1] = h1.x; ah[mt][2] = h0.y; ah[mt][3] = h1.y;
                al[mt][0] = l0.x; al[mt][1] = l1.x; al[mt][2] = l0.y; al[mt][3] = l1.y;
            }
            #pragma unroll
            for (int nt = 0; nt < 4; ++nt) {
                int n = wn + nt * 8 + grp;
                uint2 bh2 = *(const uint2*)(bufc + 24576 + n * 96 + kbyte);
                uint2 bl2 = *(const uint2*)(bufc + 30720 + n * 96 + kbyte);
                #pragma unroll
                for (int mt = 0; mt < 2; ++mt) {
                    MMA_BF16(acc[mt][nt], ah[mt][0], ah[mt][1], ah[mt][2], ah[mt][3],
                             bh2.x, bh2.y);
                    MMA_BF16(acc[mt][nt], ah[mt][0], ah[mt][1], ah[mt][2], ah[mt][3],
                             bl2.x, bl2.y);
                    MMA_BF16(acc[mt][nt], al[mt][0], al[mt][1], al[mt][2], al[mt][3],
                             bh2.x, bh2.y);
                }
            }
        }
        __syncthreads();
    }

    #pragma unroll
    for (int nt = 0; nt < 4; ++nt) {
        int col = colBase + wn + nt * 8 + tig * 2;
        float b0 = __ldg(&bias[col]);
        float b1 = __ldg(&bias[col + 1]);
        #pragma unroll
        for (int mt = 0; mt < 2; ++mt) {
            int row = rowBase + wm + mt * 16 + grp;
            *(float2*)&Yf[(size_t)row       * 512 + col] =
                make_float2(acc[mt][nt][0] + b0, acc[mt][nt][1] + b1);
            *(float2*)&Yf[(size_t)(row + 8) * 512 + col] =
                make_float2(acc[mt][nt][2] + b0, acc[mt][nt][3] + b1);
        }
    }
}

// ---------------------------------------------------------------------------
// Tensor-core flash attention v7: fp16 everywhere inside.
// QK: 2-pass f16 (Qh*K + Ql*K).  AV: 1-pass f16 (P*V).  96 MMAs/warp-iter.
// Smem: buf[2] of 20480  {K 0..10240 | V 10240..20480}.  40960 total.
// ---------------------------------------------------------------------------
constexpr int ATTN_SMEM_B = 40960;

__global__ __launch_bounds__(256, 2)
void attn_tc(const __half* __restrict__ qh, const __half* __restrict__ ql,
             const __half* __restrict__ kf, const __half* __restrict__ vtf,
             const __half* __restrict__ heat,
             __nv_bfloat16* __restrict__ yh, __nv_bfloat16* __restrict__ yl) {
    extern __shared__ char smem[];
    const uint32_t sb = smem_u32(smem);

    const int b   = blockIdx.z;
    const int h   = blockIdx.y;
    const int q0  = blockIdx.x * 128;
    const int tid = threadIdx.x;
    const int w    = tid >> 5;
    const int lane = tid & 31;
    const int grp  = lane >> 2;
    const int tig  = lane & 3;

    const int sr = tid >> 2;           // 0..63 row
    const int sc = (tid & 3) * 2;      // chunk base (2 chunks of 16B per array)

    auto issue_tile = [&](uint32_t bb, int c0) {
        size_t ksrc = (size_t)(b * NC + c0 + sr) * 512 + h * 64;
        size_t vsrc = ((size_t)(b * H_ + h) * 64 + sr) * NC + c0;
        uint32_t kd = bb + sr * 160;
        uint32_t vd = bb + 10240 + sr * 160;
        #pragma unroll
        for (int j = 0; j < 2; ++j) {
            int ch = sc + j;
            CP16(kd + ch * 16, kf  + ksrc + ch * 8);
            CP16(vd + ch * 16, vtf + vsrc + ch * 8);
        }
        CP_COMMIT();
    };

    const int qrow0 = b * NQ + q0 + w * 16 + grp;
    uint32_t qfh[4][4], qfl[4][4];
    #pragma unroll
    for (int ks = 0; ks < 4; ++ks) {
        size_t e0 = (size_t)qrow0 * 512 + h * 64 + ks * 16 + tig * 4;
        size_t e1 = e0 + (size_t)8 * 512;
        uint2 h0 = *(const uint2*)(qh + e0);
        uint2 h1 = *(const uint2*)(qh + e1);
        uint2 l0v = *(const uint2*)(ql + e0);
        uint2 l1v = *(const uint2*)(ql + e1);
        qfh[ks][0] = h0.x; qfh[ks][1] = h1.x; qfh[ks][2] = h0.y; qfh[ks][3] = h1.y;
        qfl[ks][0] = l0v.x; qfl[ks][1] = l1v.x; qfl[ks][2] = l0v.y; qfl[ks][3] = l1v.y;
    }

    float acc[8][4];
    #pragma unroll
    for (int m = 0; m < 8; ++m)
        #pragma unroll
        for (int r = 0; r < 4; ++r) acc[m][r] = 0.f;
    float lq0 = 0.f, lq8 = 0.f;

    const __half* hb0 = heat + (size_t)qrow0 * NC;
    const __half* hb1 = hb0 + (size_t)8 * NC;

    auto qk_chunk = [&](const char* bufc, int kc, float* s0, float* s1) {
        #pragma unroll
        for (int ks = 0; ks < 4; ++ks) {
            int r0 = (kc * 16 + grp) * 160 + ks * 32 + tig * 8;
            int r1 = r0 + 8 * 160;
            uint2 k0 = *(const uint2*)(bufc + r0);
            uint2 k1 = *(const uint2*)(bufc + r1);
            MMA_F16(s0, qfh[ks][0], qfh[ks][1], qfh[ks][2], qfh[ks][3], k0.x, k0.y);
            MMA_F16(s0, qfl[ks][0], qfl[ks][1], qfl[ks][2], qfl[ks][3], k0.x, k0.y);
            MMA_F16(s1, qfh[ks][0], qfh[ks][1], qfh[ks][2], qfh[ks][3], k1.x, k1.y);
            MMA_F16(s1, qfl[ks][0], qfl[ks][1], qfl[ks][2], qfl[ks][3], k1.x, k1.y);
        }
    };

    issue_tile(sb, 0);

    for (int it = 0; it < 64; ++it) {
        const int cur = it & 1;
        const char* bufc = smem + cur * 20480;
        if (it < 63) issue_tile(sb + (cur ^ 1) * 20480, (it + 1) * 64);
        if (it < 63) asm volatile("cp.async.wait_group 1;" ::: "memory");
        else         asm volatile("cp.async.wait_group 0;" ::: "memory");
        __syncthreads();

        const int c0 = it * 64;
        uint32_t HA0 = *(const uint32_t*)(hb0 + c0 + tig * 2);
        uint32_t HA1 = *(const uint32_t*)(hb1 + c0 + tig * 2);
        uint32_t HB0 = *(const uint32_t*)(hb0 + c0 + 8 + tig * 2);
        uint32_t HB1 = *(const uint32_t*)(hb1 + c0 + 8 + tig * 2);

        float s0[4] = {0.f, 0.f, 0.f, 0.f};
        float s1[4] = {0.f, 0.f, 0.f, 0.f};
        qk_chunk(bufc, 0, s0, s1);

        #pragma unroll
        for (int kc = 0; kc < 4; ++kc) {
            float2 ha0 = __half22float2(*(const __half2*)&HA0);
            float2 ha1 = __half22float2(*(const __half2*)&HA1);
            float2 hc0 = __half22float2(*(const __half2*)&HB0);
            float2 hc1 = __half22float2(*(const __half2*)&HB1);
            if (kc < 3) {
                int nb = c0 + (kc + 1) * 16 + tig * 2;
                HA0 = *(const uint32_t*)(hb0 + nb);
                HA1 = *(const uint32_t*)(hb1 + nb);
                HB0 = *(const uint32_t*)(hb0 + nb + 8);
                HB1 = *(const uint32_t*)(hb1 + nb + 8);
            }

            // ---- exp + pack P as fp16 ----
            float e00 = __expf(s0[0] + ha0.x);
            float e01 = __expf(s0[1] + ha0.y);
            float e10 = __expf(s0[2] + ha1.x);
            float e11 = __expf(s0[3] + ha1.y);
            lq0 += e00 + e01;
            lq8 += e10 + e11;
            float f00 = __expf(s1[0] + hc0.x);
            float f01 = __expf(s1[1] + hc0.y);
            float f10 = __expf(s1[2] + hc1.x);
            float f11 = __expf(s1[3] + hc1.y);
            lq0 += f00 + f01;
            lq8 += f10 + f11;
            uint32_t a0 = h2u(__floats2half2_rn(e00, e01));
            uint32_t a1 = h2u(__floats2half2_rn(e10, e11));
            uint32_t a2 = h2u(__floats2half2_rn(f00, f01));
            uint32_t a3 = h2u(__floats2half2_rn(f10, f11));

            float t0[4] = {0.f, 0.f, 0.f, 0.f};
            float t1[4] = {0.f, 0.f, 0.f, 0.f};
            if (kc < 3) qk_chunk(bufc, kc + 1, t0, t1);

            // ---- AV (1-pass f16: P*V) ----
            #pragma unroll
            for (int m = 0; m < 8; ++m) {
                int boff = 10240 + (m * 8 + grp) * 160 + kc * 32 + tig * 8;
                uint2 v2 = *(const uint2*)(bufc + boff);
                MMA_F16(acc[m], a0, a1, a2, a3, v2.x, v2.y);
            }

            #pragma unroll
            for (int r = 0; r < 4; ++r) { s0[r] = t0[r]; s1[r] = t1[r]; }
        }
        __syncthreads();
    }

    lq0 += __shfl_xor_sync(0xffffffffu, lq0, 1);
    lq0 += __shfl_xor_sync(0xffffffffu, lq0, 2);
    lq8 += __shfl_xor_sync(0xffffffffu, lq8, 1);
    lq8 += __shfl_xor_sync(0xffffffffu, lq8, 2);
    float i0 = 1.0f / lq0;
    float i1 = 1.0f / lq8;

    size_t yr0 = (size_t)qrow0 * 512 + h * 64;
    size_t yr1 = yr0 + (size_t)8 * 512;
    #pragma unroll
    for (int nt = 0; nt < 8; ++nt) {
        int ccp = (nt >> 1) * 16 + (nt & 1) * 2 + tig * 4;   // d-permuted
        float v00 = acc[nt][0] * i0, v01 = acc[nt][1] * i0;
        float v10 = acc[nt][2] * i1, v11 = acc[nt][3] * i1;
        __nv_bfloat162 h0 = __floats2bfloat162_rn(v00, v01);
        __nv_bfloat162 h1 = __floats2bfloat162_rn(v10, v11);
        __nv_bfloat162 l0v = __floats2bfloat162_rn(v00 - __bfloat162float(h0.x),
                                                   v01 - __bfloat162float(h0.y));
        __nv_bfloat162 l1v = __floats2bfloat162_rn(v10 - __bfloat162float(h1.x),
                                                   v11 - __bfloat162float(h1.y));
        *(uint32_t*)&yh[yr0 + ccp] = b2u(h0);
        *(uint32_t*)&yh[yr1 + ccp] = b2u(h1);
        *(uint32_t*)&yl[yr0 + ccp] = b2u(l0v);
        *(uint32_t*)&yl[yr1 + ccp] = b2u(l1v);
    }
}

// ---------------------------------------------------------------------------
// Launch (attn_tc at index 3 for ncu).
// ---------------------------------------------------------------------------
extern "C" void kernel_launch(void* const* d_in, const int* in_sizes, int n_in,
                              void* d_out, int out_size) {
    (void)in_sizes; (void)n_in; (void)out_size;
    const float* x_ctx     = (const float*)d_in[0];
    const float* x_query   = (const float*)d_in[1];
    const float* pos_ctx   = (const float*)d_in[2];
    const float* pos_query = (const float*)d_in[3];
    const float* Wq = (const float*)d_in[4];
    const float* bq = (const float*)d_in[5];
    const float* Wk = (const float*)d_in[6];
    const float* bk = (const float*)d_in[7];
    const float* Wv = (const float*)d_in[8];
    const float* bv = (const float*)d_in[9];
    const float* Wo = (const float*)d_in[10];
    const float* bo = (const float*)d_in[11];
    float* out = (float*)d_out;

    __half *gh, *gqh, *gql, *gkf, *gvtf;
    __nv_bfloat16 *gxqh, *gxql, *gxch, *gxcl, *gwh, *gwl, *gyh, *gyl;
    cudaGetSymbolAddress((void**)&gh,   g_heat);
    cudaGetSymbolAddress((void**)&gxqh, g_xqh);
    cudaGetSymbolAddress((void**)&gxql, g_xql);
    cudaGetSymbolAddress((void**)&gxch, g_xch);
    cudaGetSymbolAddress((void**)&gxcl, g_xcl);
    cudaGetSymbolAddress((void**)&gwh,  g_wh);
    cudaGetSymbolAddress((void**)&gwl,  g_wl);
    cudaGetSymbolAddress((void**)&gqh,  g_qh);
    cudaGetSymbolAddress((void**)&gql,  g_ql);
    cudaGetSymbolAddress((void**)&gkf,  g_kf);
    cudaGetSymbolAddress((void**)&gvtf, g_vtf);
    cudaGetSymbolAddress((void**)&gyh,  g_yh);
    cudaGetSymbolAddress((void**)&gyl,  g_yl);

    cudaFuncSetAttribute(attn_tc,
                         cudaFuncAttributeMaxDynamicSharedMemorySize, ATTN_SMEM_B);
    cudaFuncSetAttribute(proj_qkv,
                         cudaFuncAttributeMaxDynamicSharedMemorySize, GEMM_SMEM_B);
    cudaFuncSetAttribute(gemm_o,
                         cudaFuncAttributeMaxDynamicSharedMemorySize, GEMM_SMEM_B);

    // launch 0
    split_all<<<(B_ * NQ * CE + B_ * NC * CE) / 1024 + 4 * (CE * CE) / 1024, 256>>>(
        x_query, x_ctx, Wq, Wk, Wv, Wo, gxqh, gxql, gxch, gxcl, gwh, gwl);
    // launch 1
    heat_precompute<<<dim3(NQ, B_), 256>>>(pos_ctx, pos_query, gh);
    // launch 2
    proj_qkv<<<dim3(8, 64, 3), 256, GEMM_SMEM_B>>>(
        gxqh, gxql, gxch, gxcl, gwh, gwl, bq, bk, bv,
        gqh, gql, gkf, gvtf);
    // launch 3: attention (profiled)
    attn_tc<<<dim3(NQ / 128, H_, B_), 256, ATTN_SMEM_B>>>(
        gqh, gql, gkf, gvtf, gh, gyh, gyl);
    // launch 4
    gemm_o<<<dim3(8, (B_ * NQ) / 128), 256, GEMM_SMEM_B>>>(
        gyh, gyl, gwh + 3 * CE * CE, gwl + 3 * CE * CE, bo, out);
}